// round 9
// baseline (speedup 1.0000x reference)
#include <cuda_runtime.h>
#include <cuda_bf16.h>
#include <float.h>
#include <stdint.h>

// Problem constants
#define B   4
#define L   4096
#define HD  512
#define H   8
#define D   64
#define S   45
#define U   45
#define BL  (B * L)            // 16384
#define BH  (B * H)            // 32
#define KCH 8                  // K-split chunks for PV

// GEMM tiling (legacy mma.sync path)
#define GTM 256
#define GTN 128
#define GBK 32
#define A_ST (256 * 40)        // halfwords per A stage (40-hw padded rows)
#define B_ST (32 * 136)        // halfwords per B stage (136-hw padded rows)
#define GSMEM ((3 * (A_ST + B_ST)) * 2)   // bytes = 87552

// ---------------- device scratch (static; no runtime allocation) ----------------
__device__ __nv_bfloat16 g_x0[BL * HD];
__device__ __nv_bfloat16 g_x1[BL * HD];
__device__ __nv_bfloat16 g_x2[BL * HD];
__device__ __nv_bfloat16 g_W2qk[3072 * 1024];   // [Ktot=3072][N=1024] stacked [Wq|Wk]
__device__ __nv_bfloat16 g_W2v[1536 * 512];     // [Ktot=1536][N=512]
__device__ __nv_bfloat16 g_W2o[1536 * 512];
__device__ __nv_bfloat16 g_c0[BL * HD];         // context hi
__device__ __nv_bfloat16 g_c1[BL * HD];         // context lo
__device__ float g_Q[BL * HD];
__device__ float g_K[BL * HD];
__device__ float g_V[BL * HD];
__device__ float g_M[BH * L];
__device__ int   g_topidx[BH * U];
__device__ float g_scores[BH * U * L];
__device__ float g_vmeanpart[BH * 8 * D];
__device__ float g_vmean[BH * D];
__device__ float g_ctxpart[BH * KCH * U * D];
__device__ float g_ctxsel[BH * U * D];

static __device__ __forceinline__ unsigned short bf16u(__nv_bfloat16 v) {
    return *(unsigned short*)&v;
}
__device__ __forceinline__ uint32_t smem_u32(const void* p) {
    uint32_t a;
    asm("{ .reg .u64 t; cvta.to.shared.u64 t, %1; cvt.u32.u64 %0, t; }" : "=r"(a) : "l"(p));
    return a;
}
__device__ __forceinline__ void cp16(uint32_t dst, const void* src) {
    asm volatile("cp.async.cg.shared.global [%0], [%1], 16;" :: "r"(dst), "l"(src));
}

// ---------------- split x into 3 bf16 residual levels ----------------
__global__ __launch_bounds__(256) void split_x_kernel(const float* __restrict__ x) {
    size_t i = ((size_t)blockIdx.x * 256 + threadIdx.x) * 4;
    float4 v = *(const float4*)(x + i);
    float vv[4] = {v.x, v.y, v.z, v.w};
    unsigned short h0[4], h1[4], h2[4];
#pragma unroll
    for (int j = 0; j < 4; j++) {
        __nv_bfloat16 b0 = __float2bfloat16_rn(vv[j]);
        float r1 = vv[j] - __bfloat162float(b0);
        __nv_bfloat16 b1 = __float2bfloat16_rn(r1);
        __nv_bfloat16 b2 = __float2bfloat16_rn(r1 - __bfloat162float(b1));
        h0[j] = bf16u(b0); h1[j] = bf16u(b1); h2[j] = bf16u(b2);
    }
    uint2 p;
    p.x = h0[0] | ((uint32_t)h0[1] << 16); p.y = h0[2] | ((uint32_t)h0[3] << 16);
    *(uint2*)&g_x0[i] = p;
    p.x = h1[0] | ((uint32_t)h1[1] << 16); p.y = h1[2] | ((uint32_t)h1[3] << 16);
    *(uint2*)&g_x1[i] = p;
    p.x = h2[0] | ((uint32_t)h2[1] << 16); p.y = h2[2] | ((uint32_t)h2[3] << 16);
    *(uint2*)&g_x2[i] = p;
}

// ---------------- build stacked split-W matrices [Ktot][N] ----------------
__global__ __launch_bounds__(256) void build_w2_kernel(const float* __restrict__ W,
                                                       __nv_bfloat16* __restrict__ out,
                                                       int outW, int colOff,
                                                       int wsel, int nsec) {
    int id = blockIdx.x * 256 + threadIdx.x;   // < 512*512
    int r = id >> 9, c = id & 511;
    float v = W[id];
    __nv_bfloat16 b0 = __float2bfloat16_rn(v);
    float r1 = v - __bfloat162float(b0);
    __nv_bfloat16 b1 = __float2bfloat16_rn(r1);
    __nv_bfloat16 b2 = __float2bfloat16_rn(r1 - __bfloat162float(b1));
    for (int t = 0; t < nsec; t++) {
        int s = (wsel >> (2 * t)) & 3;
        out[(size_t)(t * 512 + r) * outW + colOff + c] = (s == 0) ? b0 : ((s == 1) ? b1 : b2);
    }
}

// ---------------- bf16 split GEMM via mma.sync, cp.async 3-stage pipeline ----------------
// CTA 256x128, BK=32, 8 warps as 4x2 (64x64 warp tiles).
__global__ __launch_bounds__(256, 1) void gemm_bf16(
    const __nv_bfloat16* __restrict__ A0, const __nv_bfloat16* __restrict__ A1,
    const __nv_bfloat16* __restrict__ A2,
    const __nv_bfloat16* __restrict__ W2, int Nw, int Ktot, int asel,
    float* __restrict__ o0, float* __restrict__ o1)
{
    extern __shared__ __nv_bfloat16 sh[];
    __nv_bfloat16* Abase = sh;                 // 3 stages of [256][40]
    __nv_bfloat16* Bbase = sh + 3 * A_ST;      // 3 stages of [32][136]

    int tid = threadIdx.x;
    int warp = tid >> 5, lane = tid & 31;
    int bm = blockIdx.y * GTM;
    int bn = blockIdx.x * GTN;
    int wm = (warp >> 1) * 64;
    int wn = (warp & 1) * 64;
    int nch = Ktot / GBK;

    float acc[4][8][4];
#pragma unroll
    for (int mi = 0; mi < 4; mi++)
#pragma unroll
        for (int ni = 0; ni < 8; ni++)
#pragma unroll
            for (int r = 0; r < 4; r++) acc[mi][ni][r] = 0.0f;

    // per-thread load offsets
    int aRow = tid >> 2;            // 0..63 (x4 chunks -> 256 rows via j)
    int aC8  = (tid & 3) * 8;       // hw col 0,8,16,24
    int bRow = tid >> 4;            // 0..15 (x2 -> 32 rows via j)
    int bC8  = (tid & 15) * 8;      // hw col 0..120

    auto load_stage = [&](int it, int st) {
        int kk0 = it * GBK;
        int sec = kk0 >> 9;
        int s = (asel >> (2 * sec)) & 3;
        const __nv_bfloat16* Asrc = (s == 0) ? A0 : ((s == 1) ? A1 : A2);
        int scol = kk0 & 511;
        __nv_bfloat16* Ab = Abase + st * A_ST;
        __nv_bfloat16* Bb = Bbase + st * B_ST;
#pragma unroll
        for (int j = 0; j < 4; j++) {
            int r = aRow + j * 64;
            cp16(smem_u32(Ab + r * 40 + aC8),
                 Asrc + (size_t)(bm + r) * HD + scol + aC8);
        }
#pragma unroll
        for (int j = 0; j < 2; j++) {
            int r = bRow + j * 16;
            cp16(smem_u32(Bb + r * 136 + bC8),
                 W2 + (size_t)(kk0 + r) * Nw + bn + bC8);
        }
        asm volatile("cp.async.commit_group;" ::: "memory");
    };

    load_stage(0, 0);
    if (nch > 1) load_stage(1, 1);

    for (int it = 0; it < nch; it++) {
        int st = it % 3;
        asm volatile("cp.async.wait_group 1;" ::: "memory");
        __syncthreads();                       // stage it visible; stage (it+2)%3 free
        if (it + 2 < nch) load_stage(it + 2, (it + 2) % 3);

        __nv_bfloat16* Ab = Abase + st * A_ST;
        __nv_bfloat16* Bb = Bbase + st * B_ST;
#pragma unroll
        for (int ks = 0; ks < GBK; ks += 16) {
            uint32_t af[4][4], bfr[8][2];
#pragma unroll
            for (int mi = 0; mi < 4; mi++) {
                uint32_t addr = smem_u32(
                    Ab + (wm + mi * 16 + (lane & 15)) * 40 + ks + ((lane >> 4) << 3));
                asm volatile("ldmatrix.sync.aligned.m8n8.x4.shared.b16 {%0,%1,%2,%3}, [%4];\n"
                             : "=r"(af[mi][0]), "=r"(af[mi][1]), "=r"(af[mi][2]), "=r"(af[mi][3])
                             : "r"(addr));
            }
#pragma unroll
            for (int ni = 0; ni < 8; ni++) {
                uint32_t addr = smem_u32(Bb + (ks + (lane & 15)) * 136 + wn + ni * 8);
                asm volatile("ldmatrix.sync.aligned.m8n8.x2.trans.shared.b16 {%0,%1}, [%2];\n"
                             : "=r"(bfr[ni][0]), "=r"(bfr[ni][1]) : "r"(addr));
            }
#pragma unroll
            for (int mi = 0; mi < 4; mi++)
#pragma unroll
                for (int ni = 0; ni < 8; ni++) {
                    asm volatile(
                        "mma.sync.aligned.m16n8k16.row.col.f32.bf16.bf16.f32 "
                        "{%0,%1,%2,%3}, {%4,%5,%6,%7}, {%8,%9}, {%0,%1,%2,%3};\n"
                        : "+f"(acc[mi][ni][0]), "+f"(acc[mi][ni][1]),
                          "+f"(acc[mi][ni][2]), "+f"(acc[mi][ni][3])
                        : "r"(af[mi][0]), "r"(af[mi][1]), "r"(af[mi][2]), "r"(af[mi][3]),
                          "r"(bfr[ni][0]), "r"(bfr[ni][1]));
                }
        }
        __syncthreads();                       // done reading stage it before its reuse
    }

    // epilogue: 128-wide column tile -> one of two 512-wide outputs
    float* O = (bn >= 512) ? o1 : o0;
    int nb0 = bn & 511;
#pragma unroll
    for (int mi = 0; mi < 4; mi++) {
        int r0 = bm + wm + mi * 16 + (lane >> 2);
#pragma unroll
        for (int ni = 0; ni < 8; ni++) {
            int c = nb0 + wn + ni * 8 + ((lane & 3) << 1);
            float2 v0 = make_float2(acc[mi][ni][0], acc[mi][ni][1]);
            float2 v1 = make_float2(acc[mi][ni][2], acc[mi][ni][3]);
            *(float2*)&O[(size_t)r0 * HD + c] = v0;
            *(float2*)&O[(size_t)(r0 + 8) * HD + c] = v1;
        }
    }
}

// ---------------- v mean over L per (b,h,d) ----------------
__global__ __launch_bounds__(256) void vmean_part_kernel() {
    int bh = blockIdx.x & 31, part = blockIdx.x >> 5;
    int b = bh >> 3, h = bh & 7;
    int t = threadIdx.x;
    int d = t & 63, sub = t >> 6;
    const float* base = g_V + (size_t)b * L * HD + h * D + d;
    float s = 0.0f;
    int lend = (part + 1) * 512;
    for (int l = part * 512 + sub; l < lend; l += 4) s += base[(size_t)l * HD];
    __shared__ float sm[256];
    sm[t] = s;
    __syncthreads();
    if (t < 64)
        g_vmeanpart[(bh * 8 + part) * D + t] = sm[t] + sm[t + 64] + sm[t + 128] + sm[t + 192];
}

__global__ __launch_bounds__(256) void vmean_reduce_kernel() {
    int i = blockIdx.x * 256 + threadIdx.x;
    if (i >= BH * D) return;
    int bh = i >> 6, d = i & 63;
    float s = 0.0f;
#pragma unroll
    for (int p = 0; p < 8; p++) s += g_vmeanpart[(bh * 8 + p) * D + d];
    g_vmean[i] = s * (1.0f / (float)L);
}

// ---------------- M[b,h,l] = max_s(qk) - mean_s(qk) ----------------
// Warp per (b,l,h); half-warp per sample; 4 dims/lane via float4.
__global__ __launch_bounds__(256) void compute_M_kernel(const int* __restrict__ idx) {
    int bl = blockIdx.x;
    int b = bl >> 12;
    int l = bl & (L - 1);
    int h = threadIdx.x >> 5;
    int lane = threadIdx.x & 31;
    int half = lane >> 4, sl = lane & 15;

    __shared__ int sidx[S];
    if (threadIdx.x < S) sidx[threadIdx.x] = idx[l * S + threadIdx.x];
    __syncthreads();

    float4 q = *(const float4*)(g_Q + (size_t)bl * HD + h * D + sl * 4);

    float mx = -FLT_MAX, sum = 0.0f;
#pragma unroll 1
    for (int t = 0; t < 23; t++) {
        int s = 2 * t + half;
        bool ok = (s < S);
        int j = sidx[ok ? s : 0];
        float4 kk = *(const float4*)(g_K + ((size_t)b * L + j) * HD + h * D + sl * 4);
        float p = q.x * kk.x + q.y * kk.y + q.z * kk.z + q.w * kk.w;
#pragma unroll
        for (int o = 1; o < 16; o <<= 1) p += __shfl_xor_sync(0xffffffffu, p, o);
        if (ok) { mx = fmaxf(mx, p); sum += p; }
    }
    float mxo  = __shfl_xor_sync(0xffffffffu, mx, 16);
    float sumo = __shfl_xor_sync(0xffffffffu, sum, 16);
    mx = fmaxf(mx, mxo);
    sum += sumo;
    if (lane == 0)
        g_M[((size_t)b * H + h) * L + l] = mx - sum * (1.0f / (float)S);
}

// ---------------- top-45 per (b,h), lowest-index tie-break ----------------
__global__ __launch_bounds__(256) void topk_kernel() {
    int bh = blockIdx.x;
    __shared__ float sv[L];
    __shared__ float rv[256];
    __shared__ int   ri[256];
    int t = threadIdx.x;
    const float* Mrow = g_M + (size_t)bh * L;
    for (int i = t; i < L; i += 256) sv[i] = Mrow[i];
    __syncthreads();
    for (int u = 0; u < U; u++) {
        float best = -FLT_MAX;
        int bi = L;
        for (int i = t; i < L; i += 256) {
            float v = sv[i];
            if (v > best) { best = v; bi = i; }
        }
        rv[t] = best; ri[t] = bi;
        __syncthreads();
        for (int s = 128; s; s >>= 1) {
            if (t < s) {
                if (rv[t + s] > rv[t] || (rv[t + s] == rv[t] && ri[t + s] < ri[t])) {
                    rv[t] = rv[t + s]; ri[t] = ri[t + s];
                }
            }
            __syncthreads();
        }
        if (t == 0) {
            g_topidx[bh * U + u] = ri[0];
            sv[ri[0]] = -FLT_MAX;
        }
        __syncthreads();
    }
}

// ---------------- scores[bh,u,l] = (Qr . k_l) / 8 ----------------
__global__ __launch_bounds__(256) void scores_kernel() {
    int bh = blockIdx.y;
    int b = bh >> 3, h = bh & 7;
    int l0 = blockIdx.x * 128;
    __shared__ float Qs[U][65];
    __shared__ float Ks[128][65];
    int t = threadIdx.x;

    for (int i = t; i < U * D; i += 256) {
        int u = i >> 6, d = i & 63;
        int li = g_topidx[bh * U + u];
        Qs[u][d] = g_Q[((size_t)b * L + li) * HD + h * D + d];
    }
    for (int i = t; i < 128 * D; i += 256) {
        int r = i >> 6, d = i & 63;
        Ks[r][d] = g_K[((size_t)b * L + l0 + r) * HD + h * D + d];
    }
    __syncthreads();

    for (int i = t; i < U * 128; i += 256) {
        int u = i >> 7, l = i & 127;
        float acc = 0.0f;
#pragma unroll
        for (int d = 0; d < D; d++) acc += Qs[u][d] * Ks[l][d];
        g_scores[((size_t)bh * U + u) * L + l0 + l] = acc * 0.125f;
    }
}

// ---------------- softmax over L per (bh,u) row; in place ----------------
__global__ __launch_bounds__(256) void softmax_kernel() {
    size_t row = blockIdx.x;
    float* p = g_scores + row * L;
    __shared__ float red[256];
    int t = threadIdx.x;

    float mx = -FLT_MAX;
    for (int i = t; i < L; i += 256) mx = fmaxf(mx, p[i]);
    red[t] = mx;
    __syncthreads();
    for (int s = 128; s; s >>= 1) { if (t < s) red[t] = fmaxf(red[t], red[t + s]); __syncthreads(); }
    mx = red[0];
    __syncthreads();

    float sum = 0.0f;
    for (int i = t; i < L; i += 256) {
        float e = __expf(p[i] - mx);
        p[i] = e;
        sum += e;
    }
    red[t] = sum;
    __syncthreads();
    for (int s = 128; s; s >>= 1) { if (t < s) red[t] += red[t + s]; __syncthreads(); }
    float inv = 1.0f / red[0];
    __syncthreads();
    for (int i = t; i < L; i += 256) p[i] *= inv;
}

// ---------------- PV partial over L chunks ----------------
__global__ __launch_bounds__(320) void ctx_partial_kernel() {
    int kc = blockIdx.x, bh = blockIdx.y;
    int b = bh >> 3, h = bh & 7;
    __shared__ float As[U][65];
    __shared__ float Vs[64][65];
    int t = threadIdx.x;
    int d = t & 63, ug = t >> 6;

    float acc[9];
#pragma unroll
    for (int r = 0; r < 9; r++) acc[r] = 0.0f;

    int lbase = kc * (L / KCH);
    for (int lt = 0; lt < L / KCH; lt += 64) {
        for (int i = t; i < 64 * 64; i += 320) {
            int r = i >> 6, dd = i & 63;
            Vs[r][dd] = g_V[((size_t)b * L + lbase + lt + r) * HD + h * D + dd];
        }
        for (int i = t; i < U * 64; i += 320) {
            int u = i >> 6, ll = i & 63;
            As[u][ll] = g_scores[((size_t)bh * U + u) * L + lbase + lt + ll];
        }
        __syncthreads();
#pragma unroll 8
        for (int ll = 0; ll < 64; ll++) {
            float vv = Vs[ll][d];
#pragma unroll
            for (int r = 0; r < 9; r++) acc[r] += As[ug + 5 * r][ll] * vv;
        }
        __syncthreads();
    }
#pragma unroll
    for (int r = 0; r < 9; r++)
        g_ctxpart[(((size_t)bh * KCH) + kc) * (U * D) + (ug + 5 * r) * D + d] = acc[r];
}

__global__ __launch_bounds__(256) void ctx_reduce_kernel() {
    int i = blockIdx.x * 256 + threadIdx.x;
    if (i >= BH * U * D) return;
    int bh = i / (U * D), rem = i % (U * D);
    float s = 0.0f;
#pragma unroll
    for (int kc = 0; kc < KCH; kc++)
        s += g_ctxpart[((size_t)bh * KCH + kc) * (U * D) + rem];
    g_ctxsel[i] = s;
}

// ---------------- context (bf16 hi/lo) ----------------
__global__ __launch_bounds__(256) void fill_context_kernel() {
    size_t e = (size_t)blockIdx.x * 256 + threadIdx.x;
    int col = (int)(e & (HD - 1));
    size_t bl = e >> 9;
    int b = (int)(bl >> 12);
    int h = col >> 6, d = col & 63;
    float v = g_vmean[(b * H + h) * D + d];
    __nv_bfloat16 hh = __float2bfloat16_rn(v);
    g_c0[e] = hh;
    g_c1[e] = __float2bfloat16_rn(v - __bfloat162float(hh));
}

__global__ __launch_bounds__(64) void scatter_kernel() {
    int bhu = blockIdx.x;
    int d = threadIdx.x;
    int bh = bhu / U, u = bhu % U;
    int b = bh >> 3, h = bh & 7;
    int li = g_topidx[bh * U + u];
    float v = g_ctxsel[(size_t)bhu * D + d];
    __nv_bfloat16 hh = __float2bfloat16_rn(v);
    size_t e = ((size_t)b * L + li) * HD + h * D + d;
    g_c0[e] = hh;
    g_c1[e] = __float2bfloat16_rn(v - __bfloat162float(hh));
}

// ---------------- launch ----------------
extern "C" void kernel_launch(void* const* d_in, const int* in_sizes, int n_in,
                              void* d_out, int out_size) {
    const float* x  = (const float*)d_in[0];
    const float* Wq = (const float*)d_in[1];
    const float* Wk = (const float*)d_in[2];
    const float* Wv = (const float*)d_in[3];
    const float* Wo = (const float*)d_in[4];
    const int*   idx = (const int*)d_in[5];
    float* out = (float*)d_out;

    __nv_bfloat16 *x0, *x1, *x2, *W2qk, *W2v, *W2o, *c0, *c1;
    float *Q, *K, *V;
    cudaGetSymbolAddress((void**)&x0, g_x0);
    cudaGetSymbolAddress((void**)&x1, g_x1);
    cudaGetSymbolAddress((void**)&x2, g_x2);
    cudaGetSymbolAddress((void**)&W2qk, g_W2qk);
    cudaGetSymbolAddress((void**)&W2v,  g_W2v);
    cudaGetSymbolAddress((void**)&W2o,  g_W2o);
    cudaGetSymbolAddress((void**)&c0, g_c0);
    cudaGetSymbolAddress((void**)&c1, g_c1);
    cudaGetSymbolAddress((void**)&Q, g_Q);
    cudaGetSymbolAddress((void**)&K, g_K);
    cudaGetSymbolAddress((void**)&V, g_V);

    cudaFuncSetAttribute(gemm_bf16, cudaFuncAttributeMaxDynamicSharedMemorySize, GSMEM);

    split_x_kernel<<<(BL * HD) / 1024, 256>>>(x);
    // 6-term maps: W sections {0,1,0,2,1,0} -> 0x184 ; A sections {0,0,1,0,1,2} -> 0x910
    build_w2_kernel<<<1024, 256>>>(Wq, W2qk, 1024, 0,   0x184, 6);
    build_w2_kernel<<<1024, 256>>>(Wk, W2qk, 1024, 512, 0x184, 6);
    // 3-term maps: W {0,1,0} -> 0x4 ; A {0,0,1} -> 0x10
    build_w2_kernel<<<1024, 256>>>(Wv, W2v, 512, 0, 0x4, 3);
    build_w2_kernel<<<1024, 256>>>(Wo, W2o, 512, 0, 0x4, 3);

    // Q,K projection: 6-term
    gemm_bf16<<<dim3(1024 / GTN, BL / GTM), 256, GSMEM>>>(x0, x1, x2, W2qk, 1024, 3072, 0x910, Q, K);
    // V projection: 3-term
    gemm_bf16<<<dim3(512 / GTN, BL / GTM), 256, GSMEM>>>(x0, x1, x2, W2v, 512, 1536, 0x10, V, V);

    vmean_part_kernel<<<256, 256>>>();
    vmean_reduce_kernel<<<8, 256>>>();
    compute_M_kernel<<<BL, 256>>>(idx);
    topk_kernel<<<BH, 256>>>();

    scores_kernel<<<dim3(L / 128, BH), 256>>>();
    softmax_kernel<<<BH * U, 256>>>();
    ctx_partial_kernel<<<dim3(KCH, BH), 320>>>();
    ctx_reduce_kernel<<<(BH * U * D + 255) / 256, 256>>>();

    fill_context_kernel<<<(BL * HD) / 256, 256>>>();
    scatter_kernel<<<BH * U, 64>>>();

    // output projection: 3-term on context hi/lo
    gemm_bf16<<<dim3(512 / GTN, BL / GTM), 256, GSMEM>>>(c0, c1, c1, W2o, 512, 1536, 0x10, out, out);
}

// round 10
// speedup vs baseline: 1.1698x; 1.1698x over previous
#include <cuda_runtime.h>
#include <cuda_bf16.h>
#include <float.h>
#include <stdint.h>

// Problem constants
#define B   4
#define L   4096
#define HD  512
#define H   8
#define D   64
#define S   45
#define U   45
#define BL  (B * L)            // 16384
#define BH  (B * H)            // 32
#define FCH 8                  // L-chunks for fused attention
#define FST 65                 // smem row stride (floats), conflict-minimal

// ---------------- device scratch (static; no runtime allocation) ----------------
__device__ __nv_bfloat16 g_x0[BL * HD];
__device__ __nv_bfloat16 g_x1[BL * HD];
__device__ __nv_bfloat16 g_x2[BL * HD];
__device__ __nv_bfloat16 g_W2qk[3072 * 1024];   // [Ktot=3072][N=1024] stacked [Wq|Wk]
__device__ __nv_bfloat16 g_W2v[1536 * 512];     // [Ktot=1536][N=512]
__device__ __nv_bfloat16 g_W2o[1536 * 512];
__device__ __nv_bfloat16 g_c0[BL * HD];         // context hi
__device__ __nv_bfloat16 g_c1[BL * HD];         // context lo
__device__ float g_Q[BL * HD];
__device__ float g_K[BL * HD];
__device__ float g_V[BL * HD];
__device__ float g_M[BH * L];
__device__ int   g_topidx[BH * U];
__device__ float g_vmeanpart[BH * 8 * D];
__device__ float g_vmean[BH * D];
__device__ float g_ctxpart[BH * FCH * U * D];   // unnormalized PV partials
__device__ float g_pm[BH * FCH * U];            // per-chunk running max
__device__ float g_ps[BH * FCH * U];            // per-chunk exp-sum
__device__ float g_ctxsel[BH * U * D];

static __device__ __forceinline__ unsigned short bf16u(__nv_bfloat16 v) {
    return *(unsigned short*)&v;
}

// ---------------- split x into 3 bf16 residual levels ----------------
__global__ __launch_bounds__(256) void split_x_kernel(const float* __restrict__ x) {
    size_t i = ((size_t)blockIdx.x * 256 + threadIdx.x) * 4;
    float4 v = *(const float4*)(x + i);
    float vv[4] = {v.x, v.y, v.z, v.w};
    unsigned short h0[4], h1[4], h2[4];
#pragma unroll
    for (int j = 0; j < 4; j++) {
        __nv_bfloat16 b0 = __float2bfloat16_rn(vv[j]);
        float r1 = vv[j] - __bfloat162float(b0);
        __nv_bfloat16 b1 = __float2bfloat16_rn(r1);
        __nv_bfloat16 b2 = __float2bfloat16_rn(r1 - __bfloat162float(b1));
        h0[j] = bf16u(b0); h1[j] = bf16u(b1); h2[j] = bf16u(b2);
    }
    uint2 p;
    p.x = h0[0] | ((uint32_t)h0[1] << 16); p.y = h0[2] | ((uint32_t)h0[3] << 16);
    *(uint2*)&g_x0[i] = p;
    p.x = h1[0] | ((uint32_t)h1[1] << 16); p.y = h1[2] | ((uint32_t)h1[3] << 16);
    *(uint2*)&g_x1[i] = p;
    p.x = h2[0] | ((uint32_t)h2[1] << 16); p.y = h2[2] | ((uint32_t)h2[3] << 16);
    *(uint2*)&g_x2[i] = p;
}

// ---------------- build stacked split-W matrices [Ktot][N] ----------------
__global__ __launch_bounds__(256) void build_w2_kernel(const float* __restrict__ W,
                                                       __nv_bfloat16* __restrict__ out,
                                                       int outW, int colOff,
                                                       int wsel, int nsec) {
    int id = blockIdx.x * 256 + threadIdx.x;   // < 512*512
    int r = id >> 9, c = id & 511;
    float v = W[id];
    __nv_bfloat16 b0 = __float2bfloat16_rn(v);
    float r1 = v - __bfloat162float(b0);
    __nv_bfloat16 b1 = __float2bfloat16_rn(r1);
    __nv_bfloat16 b2 = __float2bfloat16_rn(r1 - __bfloat162float(b1));
    for (int t = 0; t < nsec; t++) {
        int s = (wsel >> (2 * t)) & 3;
        out[(size_t)(t * 512 + r) * outW + colOff + c] = (s == 0) ? b0 : ((s == 1) ? b1 : b2);
    }
}

// ---------------- bf16 split GEMM via mma.sync (R5 proven version) ----------------
// 128x128 tile, BK=32, 256 threads = 8 warps in 2x4 (64x32 warp tiles),
// double-buffered smem with register-staged global loads.
__global__ __launch_bounds__(256) void gemm_bf16(
    const __nv_bfloat16* __restrict__ A0, const __nv_bfloat16* __restrict__ A1,
    const __nv_bfloat16* __restrict__ A2,
    const __nv_bfloat16* __restrict__ W2, int Nw, int Ktot, int asel,
    float* __restrict__ o0, float* __restrict__ o1, float* __restrict__ o2)
{
    __shared__ __nv_bfloat16 As[2][128][40];
    __shared__ __nv_bfloat16 Bs[2][32][136];

    int tid = threadIdx.x;
    int warp = tid >> 5, lane = tid & 31;
    int bm = blockIdx.y * 128;
    int bn = blockIdx.x * 128;
    int wm = (warp >> 2) * 64;
    int wn = (warp & 3) * 32;

    float acc[4][4][4];
#pragma unroll
    for (int mi = 0; mi < 4; mi++)
#pragma unroll
        for (int ni = 0; ni < 4; ni++)
#pragma unroll
            for (int r = 0; r < 4; r++) acc[mi][ni][r] = 0.0f;

    int arow0 = tid >> 2;            // 0..63
    int acol0 = (tid & 3) * 8;       // 0,8,16,24
    int brow0 = tid >> 4;            // 0..15
    int bcol0 = (tid & 15) * 8;      // 0..120

    int kiter = Ktot / 32;
    uint4 ra0, ra1, rb0, rb1;

    {
        int s = asel & 3;
        const __nv_bfloat16* Asrc = (s == 0) ? A0 : ((s == 1) ? A1 : A2);
        ra0 = *(const uint4*)&Asrc[(size_t)(bm + arow0) * HD + acol0];
        ra1 = *(const uint4*)&Asrc[(size_t)(bm + 64 + arow0) * HD + acol0];
        rb0 = *(const uint4*)&W2[(size_t)brow0 * Nw + bn + bcol0];
        rb1 = *(const uint4*)&W2[(size_t)(16 + brow0) * Nw + bn + bcol0];
        *(uint4*)&As[0][arow0][acol0]      = ra0;
        *(uint4*)&As[0][64 + arow0][acol0] = ra1;
        *(uint4*)&Bs[0][brow0][bcol0]      = rb0;
        *(uint4*)&Bs[0][16 + brow0][bcol0] = rb1;
    }
    __syncthreads();

    int cur = 0;
    for (int it = 0; it < kiter; it++) {
        if (it + 1 < kiter) {
            int kk0 = (it + 1) * 32;
            int s = (asel >> (2 * (kk0 >> 9))) & 3;
            const __nv_bfloat16* Asrc = (s == 0) ? A0 : ((s == 1) ? A1 : A2);
            int scol = kk0 & 511;
            ra0 = *(const uint4*)&Asrc[(size_t)(bm + arow0) * HD + scol + acol0];
            ra1 = *(const uint4*)&Asrc[(size_t)(bm + 64 + arow0) * HD + scol + acol0];
            rb0 = *(const uint4*)&W2[(size_t)(kk0 + brow0) * Nw + bn + bcol0];
            rb1 = *(const uint4*)&W2[(size_t)(kk0 + 16 + brow0) * Nw + bn + bcol0];
        }
#pragma unroll
        for (int ks = 0; ks < 32; ks += 16) {
            uint32_t af[4][4], bfr[4][2];
#pragma unroll
            for (int mi = 0; mi < 4; mi++) {
                uint32_t addr = (uint32_t)__cvta_generic_to_shared(
                    &As[cur][wm + mi * 16 + (lane & 15)][ks + ((lane >> 4) << 3)]);
                asm volatile("ldmatrix.sync.aligned.m8n8.x4.shared.b16 {%0,%1,%2,%3}, [%4];\n"
                             : "=r"(af[mi][0]), "=r"(af[mi][1]), "=r"(af[mi][2]), "=r"(af[mi][3])
                             : "r"(addr));
            }
#pragma unroll
            for (int ni = 0; ni < 4; ni++) {
                uint32_t addr = (uint32_t)__cvta_generic_to_shared(
                    &Bs[cur][ks + (lane & 15)][wn + ni * 8]);
                asm volatile("ldmatrix.sync.aligned.m8n8.x2.trans.shared.b16 {%0,%1}, [%2];\n"
                             : "=r"(bfr[ni][0]), "=r"(bfr[ni][1]) : "r"(addr));
            }
#pragma unroll
            for (int mi = 0; mi < 4; mi++)
#pragma unroll
                for (int ni = 0; ni < 4; ni++) {
                    asm volatile(
                        "mma.sync.aligned.m16n8k16.row.col.f32.bf16.bf16.f32 "
                        "{%0,%1,%2,%3}, {%4,%5,%6,%7}, {%8,%9}, {%0,%1,%2,%3};\n"
                        : "+f"(acc[mi][ni][0]), "+f"(acc[mi][ni][1]),
                          "+f"(acc[mi][ni][2]), "+f"(acc[mi][ni][3])
                        : "r"(af[mi][0]), "r"(af[mi][1]), "r"(af[mi][2]), "r"(af[mi][3]),
                          "r"(bfr[ni][0]), "r"(bfr[ni][1]));
                }
        }
        if (it + 1 < kiter) {
            int nb = cur ^ 1;
            *(uint4*)&As[nb][arow0][acol0]      = ra0;
            *(uint4*)&As[nb][64 + arow0][acol0] = ra1;
            *(uint4*)&Bs[nb][brow0][bcol0]      = rb0;
            *(uint4*)&Bs[nb][16 + brow0][bcol0] = rb1;
            __syncthreads();
            cur ^= 1;
        }
    }

    int sec = bn >> 9;
    float* O = (sec == 0) ? o0 : ((sec == 1) ? o1 : o2);
    int nb0 = bn & 511;
#pragma unroll
    for (int mi = 0; mi < 4; mi++) {
        int r = bm + wm + mi * 16 + (lane >> 2);
#pragma unroll
        for (int ni = 0; ni < 4; ni++) {
            int c = nb0 + wn + ni * 8 + ((lane & 3) << 1);
            float2 v0 = make_float2(acc[mi][ni][0], acc[mi][ni][1]);
            float2 v1 = make_float2(acc[mi][ni][2], acc[mi][ni][3]);
            *(float2*)&O[(size_t)r * HD + c] = v0;
            *(float2*)&O[(size_t)(r + 8) * HD + c] = v1;
        }
    }
}

// ---------------- v mean over L per (b,h,d) ----------------
__global__ __launch_bounds__(256) void vmean_part_kernel() {
    int bh = blockIdx.x & 31, part = blockIdx.x >> 5;
    int b = bh >> 3, h = bh & 7;
    int t = threadIdx.x;
    int d = t & 63, sub = t >> 6;
    const float* base = g_V + (size_t)b * L * HD + h * D + d;
    float s = 0.0f;
    int lend = (part + 1) * 512;
    for (int l = part * 512 + sub; l < lend; l += 4) s += base[(size_t)l * HD];
    __shared__ float sm[256];
    sm[t] = s;
    __syncthreads();
    if (t < 64)
        g_vmeanpart[(bh * 8 + part) * D + t] = sm[t] + sm[t + 64] + sm[t + 128] + sm[t + 192];
}

__global__ __launch_bounds__(256) void vmean_reduce_kernel() {
    int i = blockIdx.x * 256 + threadIdx.x;
    if (i >= BH * D) return;
    int bh = i >> 6, d = i & 63;
    float s = 0.0f;
#pragma unroll
    for (int p = 0; p < 8; p++) s += g_vmeanpart[(bh * 8 + p) * D + d];
    g_vmean[i] = s * (1.0f / (float)L);
}

// ---------------- M[b,h,l] = max_s(qk) - mean_s(qk) (R6 exact version) ----------------
__global__ __launch_bounds__(256) void compute_M_kernel(const int* __restrict__ idx) {
    int bl = blockIdx.x;
    int b = bl >> 12;
    int l = bl & (L - 1);
    int h = threadIdx.x >> 5;
    int lane = threadIdx.x & 31;
    int half = lane >> 4, sl = lane & 15;

    __shared__ int sidx[S];
    if (threadIdx.x < S) sidx[threadIdx.x] = idx[l * S + threadIdx.x];
    __syncthreads();

    float4 q = *(const float4*)(g_Q + (size_t)bl * HD + h * D + sl * 4);

    float mx = -FLT_MAX, sum = 0.0f;
#pragma unroll 1
    for (int t = 0; t < 23; t++) {
        int s = 2 * t + half;
        bool ok = (s < S);
        int j = sidx[ok ? s : 0];
        float4 kk = *(const float4*)(g_K + ((size_t)b * L + j) * HD + h * D + sl * 4);
        float p = q.x * kk.x + q.y * kk.y + q.z * kk.z + q.w * kk.w;
#pragma unroll
        for (int o = 1; o < 16; o <<= 1) p += __shfl_xor_sync(0xffffffffu, p, o);
        if (ok) { mx = fmaxf(mx, p); sum += p; }
    }
    float mxo  = __shfl_xor_sync(0xffffffffu, mx, 16);
    float sumo = __shfl_xor_sync(0xffffffffu, sum, 16);
    mx = fmaxf(mx, mxo);
    sum += sumo;
    if (lane == 0)
        g_M[((size_t)b * H + h) * L + l] = mx - sum * (1.0f / (float)S);
}

// ---------------- top-45 per (b,h), lowest-index tie-break ----------------
__global__ __launch_bounds__(256) void topk_kernel() {
    int bh = blockIdx.x;
    __shared__ float sv[L];
    __shared__ float rv[256];
    __shared__ int   ri[256];
    int t = threadIdx.x;
    const float* Mrow = g_M + (size_t)bh * L;
    for (int i = t; i < L; i += 256) sv[i] = Mrow[i];
    __syncthreads();
    for (int u = 0; u < U; u++) {
        float best = -FLT_MAX;
        int bi = L;
        for (int i = t; i < L; i += 256) {
            float v = sv[i];
            if (v > best) { best = v; bi = i; }
        }
        rv[t] = best; ri[t] = bi;
        __syncthreads();
        for (int s = 128; s; s >>= 1) {
            if (t < s) {
                if (rv[t + s] > rv[t] || (rv[t + s] == rv[t] && ri[t + s] < ri[t])) {
                    rv[t] = rv[t + s]; ri[t] = ri[t + s];
                }
            }
            __syncthreads();
        }
        if (t == 0) {
            g_topidx[bh * U + u] = ri[0];
            sv[ri[0]] = -FLT_MAX;
        }
        __syncthreads();
    }
}

// ---------------- fused scores+softmax+PV (flash-style, per L-chunk) ----------------
// grid (FCH, BH), 256 threads. Chunk = 512 l, subtiles of 64.
__global__ __launch_bounds__(256) void attn_fused_kernel() {
    extern __shared__ float fs[];
    float* Qs   = fs;                    // 48 x FST
    float* Ks   = Qs + 48 * FST;         // 64 x FST
    float* Vs   = Ks + 64 * FST;         // 64 x FST
    float* Ss   = Vs + 64 * FST;         // 48 x FST
    float* m_sh = Ss + 48 * FST;         // 48
    float* s_sh = m_sh + 48;             // 48
    float* r_sh = s_sh + 48;             // 48

    int chunk = blockIdx.x, bh = blockIdx.y;
    int b = bh >> 3, h = bh & 7;
    int t = threadIdx.x;
    int d = t & 63, ug = t >> 6;
    int l0g = chunk * (L / FCH);

    // gather selected Q rows
    for (int i = t; i < U * 16; i += 256) {
        int u = i >> 4, c4 = (i & 15) * 4;
        int li = g_topidx[bh * U + u];
        float4 q = *(const float4*)&g_Q[((size_t)b * L + li) * HD + h * D + c4];
        Qs[u * FST + c4 + 0] = q.x;
        Qs[u * FST + c4 + 1] = q.y;
        Qs[u * FST + c4 + 2] = q.z;
        Qs[u * FST + c4 + 3] = q.w;
    }
    if (t < 48) { m_sh[t] = -FLT_MAX; s_sh[t] = 0.0f; }

    float acc[12];
#pragma unroll
    for (int r = 0; r < 12; r++) acc[r] = 0.0f;
    __syncthreads();

    for (int sub = 0; sub < 8; sub++) {
        // load K/V subtile 64x64
        for (int i = t; i < 64 * 16; i += 256) {
            int r = i >> 4, c4 = (i & 15) * 4;
            size_t base = ((size_t)b * L + l0g + sub * 64 + r) * HD + h * D + c4;
            float4 kk = *(const float4*)&g_K[base];
            Ks[r * FST + c4 + 0] = kk.x; Ks[r * FST + c4 + 1] = kk.y;
            Ks[r * FST + c4 + 2] = kk.z; Ks[r * FST + c4 + 3] = kk.w;
            float4 vv = *(const float4*)&g_V[base];
            Vs[r * FST + c4 + 0] = vv.x; Vs[r * FST + c4 + 1] = vv.y;
            Vs[r * FST + c4 + 2] = vv.z; Vs[r * FST + c4 + 3] = vv.w;
        }
        __syncthreads();

        // scores: 4u x 4l register tile per thread (192 active)
        if (t < 192) {
            int u0 = (t >> 4) * 4, ll0 = (t & 15) * 4;
            float sa[4][4];
#pragma unroll
            for (int j = 0; j < 4; j++)
#pragma unroll
                for (int jj = 0; jj < 4; jj++) sa[j][jj] = 0.0f;
            for (int dd = 0; dd < 64; dd++) {
                float qv[4], kv[4];
#pragma unroll
                for (int j = 0; j < 4; j++) qv[j] = Qs[(u0 + j) * FST + dd];
#pragma unroll
                for (int j = 0; j < 4; j++) kv[j] = Ks[(ll0 + j) * FST + dd];
#pragma unroll
                for (int j = 0; j < 4; j++)
#pragma unroll
                    for (int jj = 0; jj < 4; jj++) sa[j][jj] += qv[j] * kv[jj];
            }
#pragma unroll
            for (int j = 0; j < 4; j++)
#pragma unroll
                for (int jj = 0; jj < 4; jj++)
                    Ss[(u0 + j) * FST + ll0 + jj] = sa[j][jj] * 0.125f;
        }
        __syncthreads();

        // per-row running max / exp / sum (45 reducer threads)
        if (t < U) {
            float* row = Ss + t * FST;
            float tm = row[0];
            for (int l = 1; l < 64; l++) tm = fmaxf(tm, row[l]);
            float om = m_sh[t];
            float nm = fmaxf(om, tm);
            float rs = __expf(om - nm);
            float se = 0.0f;
            for (int l = 0; l < 64; l++) {
                float e = __expf(row[l] - nm);
                row[l] = e;
                se += e;
            }
            m_sh[t] = nm;
            s_sh[t] = s_sh[t] * rs + se;
            r_sh[t] = rs;
        }
        __syncthreads();

        // PV accumulate with rescale
#pragma unroll
        for (int r = 0; r < 12; r++) {
            int u = ug + 4 * r;
            if (u < U) {
                float a = acc[r] * r_sh[u];
                const float* e = Ss + u * FST;
#pragma unroll 8
                for (int l = 0; l < 64; l++) a += e[l] * Vs[l * FST + d];
                acc[r] = a;
            }
        }
        __syncthreads();
    }

    // write partials (unnormalized) + stats
#pragma unroll
    for (int r = 0; r < 12; r++) {
        int u = ug + 4 * r;
        if (u < U)
            g_ctxpart[((size_t)bh * FCH + chunk) * (U * D) + u * D + d] = acc[r];
    }
    if (t < U) {
        g_pm[(bh * FCH + chunk) * U + t] = m_sh[t];
        g_ps[(bh * FCH + chunk) * U + t] = s_sh[t];
    }
}

// ---------------- LSE merge across chunks ----------------
__global__ __launch_bounds__(256) void attn_merge_kernel() {
    int i = blockIdx.x * 256 + threadIdx.x;
    if (i >= BH * U * D) return;
    int bh = i / (U * D);
    int rem = i % (U * D);
    int u = rem / D;
    float gm = -FLT_MAX;
#pragma unroll
    for (int c = 0; c < FCH; c++)
        gm = fmaxf(gm, g_pm[(bh * FCH + c) * U + u]);
    float den = 0.0f, num = 0.0f;
#pragma unroll
    for (int c = 0; c < FCH; c++) {
        float w = __expf(g_pm[(bh * FCH + c) * U + u] - gm);
        den += g_ps[(bh * FCH + c) * U + u] * w;
        num += g_ctxpart[((size_t)bh * FCH + c) * (U * D) + rem] * w;
    }
    g_ctxsel[i] = num / den;
}

// ---------------- context (bf16 hi/lo) ----------------
__global__ __launch_bounds__(256) void fill_context_kernel() {
    size_t e = (size_t)blockIdx.x * 256 + threadIdx.x;
    int col = (int)(e & (HD - 1));
    size_t bl = e >> 9;
    int b = (int)(bl >> 12);
    int h = col >> 6, d = col & 63;
    float v = g_vmean[(b * H + h) * D + d];
    __nv_bfloat16 hh = __float2bfloat16_rn(v);
    g_c0[e] = hh;
    g_c1[e] = __float2bfloat16_rn(v - __bfloat162float(hh));
}

__global__ __launch_bounds__(64) void scatter_kernel() {
    int bhu = blockIdx.x;
    int d = threadIdx.x;
    int bh = bhu / U, u = bhu % U;
    int b = bh >> 3, h = bh & 7;
    int li = g_topidx[bh * U + u];
    float v = g_ctxsel[(size_t)bhu * D + d];
    __nv_bfloat16 hh = __float2bfloat16_rn(v);
    size_t e = ((size_t)b * L + li) * HD + h * D + d;
    g_c0[e] = hh;
    g_c1[e] = __float2bfloat16_rn(v - __bfloat162float(hh));
}

// ---------------- launch ----------------
extern "C" void kernel_launch(void* const* d_in, const int* in_sizes, int n_in,
                              void* d_out, int out_size) {
    const float* x  = (const float*)d_in[0];
    const float* Wq = (const float*)d_in[1];
    const float* Wk = (const float*)d_in[2];
    const float* Wv = (const float*)d_in[3];
    const float* Wo = (const float*)d_in[4];
    const int*   idx = (const int*)d_in[5];
    float* out = (float*)d_out;

    __nv_bfloat16 *x0, *x1, *x2, *W2qk, *W2v, *W2o, *c0, *c1;
    float *Q, *K, *V;
    cudaGetSymbolAddress((void**)&x0, g_x0);
    cudaGetSymbolAddress((void**)&x1, g_x1);
    cudaGetSymbolAddress((void**)&x2, g_x2);
    cudaGetSymbolAddress((void**)&W2qk, g_W2qk);
    cudaGetSymbolAddress((void**)&W2v,  g_W2v);
    cudaGetSymbolAddress((void**)&W2o,  g_W2o);
    cudaGetSymbolAddress((void**)&c0, g_c0);
    cudaGetSymbolAddress((void**)&c1, g_c1);
    cudaGetSymbolAddress((void**)&Q, g_Q);
    cudaGetSymbolAddress((void**)&K, g_K);
    cudaGetSymbolAddress((void**)&V, g_V);

    const int FSMEM = (48 * FST + 64 * FST + 64 * FST + 48 * FST + 144) * 4;
    cudaFuncSetAttribute(attn_fused_kernel, cudaFuncAttributeMaxDynamicSharedMemorySize, FSMEM);

    split_x_kernel<<<(BL * HD) / 1024, 256>>>(x);
    // 6-term maps: W sections {0,1,0,2,1,0} -> 0x184 ; A sections {0,0,1,0,1,2} -> 0x910
    build_w2_kernel<<<1024, 256>>>(Wq, W2qk, 1024, 0,   0x184, 6);
    build_w2_kernel<<<1024, 256>>>(Wk, W2qk, 1024, 512, 0x184, 6);
    // 3-term maps: W {0,1,0} -> 0x4 ; A {0,0,1} -> 0x10
    build_w2_kernel<<<1024, 256>>>(Wv, W2v, 512, 0, 0x4, 3);
    build_w2_kernel<<<1024, 256>>>(Wo, W2o, 512, 0, 0x4, 3);

    // Q,K projection: 6-term
    gemm_bf16<<<dim3(8, 128), 256>>>(x0, x1, x2, W2qk, 1024, 3072, 0x910, Q, K, K);
    // V projection: 3-term
    gemm_bf16<<<dim3(4, 128), 256>>>(x0, x1, x2, W2v, 512, 1536, 0x10, V, V, V);

    vmean_part_kernel<<<256, 256>>>();
    vmean_reduce_kernel<<<8, 256>>>();
    compute_M_kernel<<<BL, 256>>>(idx);
    topk_kernel<<<BH, 256>>>();

    attn_fused_kernel<<<dim3(FCH, BH), 256, FSMEM>>>();
    attn_merge_kernel<<<(BH * U * D + 255) / 256, 256>>>();

    fill_context_kernel<<<(BL * HD) / 256, 256>>>();
    scatter_kernel<<<BH * U, 64>>>();

    // output projection: 3-term on context hi/lo
    gemm_bf16<<<dim3(4, 128), 256>>>(c0, c1, c1, W2o, 512, 1536, 0x10, out, out, out);
}

// round 11
// speedup vs baseline: 1.4356x; 1.2273x over previous
#include <cuda_runtime.h>
#include <cuda_fp16.h>
#include <float.h>
#include <stdint.h>

// Problem constants
#define B   4
#define L   4096
#define HD  512
#define H   8
#define D   64
#define S   45
#define U   45
#define BL  (B * L)            // 16384
#define BH  (B * H)            // 32
#define FCH 8                  // L-chunks for fused attention
#define FST 65                 // smem row stride (floats)

// ---------------- device scratch (static; no runtime allocation) ----------------
__device__ __half g_x0[BL * HD];
__device__ __half g_x1[BL * HD];
__device__ __half g_W2qk[1536 * 1024];   // [Ktot=1536][N=1024] stacked [Wq|Wk]
__device__ __half g_W2v[1536 * 512];     // [Ktot=1536][N=512]
__device__ __half g_W2o[1536 * 512];
__device__ __half g_c0[BL * HD];         // context hi
__device__ __half g_c1[BL * HD];         // context lo
__device__ float g_Q[BL * HD];
__device__ float g_K[BL * HD];
__device__ float g_V[BL * HD];
__device__ float g_M[BH * L];
__device__ int   g_topidx[BH * U];
__device__ float g_vmeanpart[BH * 8 * D];
__device__ float g_vmean[BH * D];
__device__ float g_ctxpart[BH * FCH * U * D];   // unnormalized PV partials
__device__ float g_pm[BH * FCH * U];
__device__ float g_ps[BH * FCH * U];
__device__ float g_ctxsel[BH * U * D];

static __device__ __forceinline__ unsigned short h16u(__half v) {
    return *(unsigned short*)&v;
}

// ---------------- split x into 2 fp16 residual levels ----------------
__global__ __launch_bounds__(256) void split_x_kernel(const float* __restrict__ x) {
    size_t i = ((size_t)blockIdx.x * 256 + threadIdx.x) * 4;
    float4 v = *(const float4*)(x + i);
    float vv[4] = {v.x, v.y, v.z, v.w};
    unsigned short h0[4], h1[4];
#pragma unroll
    for (int j = 0; j < 4; j++) {
        __half a0 = __float2half_rn(vv[j]);
        __half a1 = __float2half_rn(vv[j] - __half2float(a0));
        h0[j] = h16u(a0); h1[j] = h16u(a1);
    }
    uint2 p;
    p.x = h0[0] | ((uint32_t)h0[1] << 16); p.y = h0[2] | ((uint32_t)h0[3] << 16);
    *(uint2*)&g_x0[i] = p;
    p.x = h1[0] | ((uint32_t)h1[1] << 16); p.y = h1[2] | ((uint32_t)h1[3] << 16);
    *(uint2*)&g_x1[i] = p;
}

// ---------------- build stacked split-W matrices [Ktot=1536][N] ----------------
// sections: {w0, w1, w0}
__global__ __launch_bounds__(256) void build_w2_kernel(const float* __restrict__ W,
                                                       __half* __restrict__ out,
                                                       int outW, int colOff) {
    int id = blockIdx.x * 256 + threadIdx.x;   // < 512*512
    int r = id >> 9, c = id & 511;
    float v = W[id];
    __half b0 = __float2half_rn(v);
    __half b1 = __float2half_rn(v - __half2float(b0));
    out[(size_t)r * outW + colOff + c] = b0;
    out[(size_t)(512 + r) * outW + colOff + c] = b1;
    out[(size_t)(1024 + r) * outW + colOff + c] = b0;
}

// ---------------- fp16 split GEMM via mma.sync (R5-proven shape) ----------------
// C = x0@W0 + x0@W1 + x1@W0 over stacked Ktot=1536.  A sections {0,0,1}.
// 128x128 tile, BK=32, 8 warps in 2x4 (64x32 warp tiles), double-buffered smem.
__global__ __launch_bounds__(256) void gemm_f16(
    const __half* __restrict__ A0, const __half* __restrict__ A1,
    const __half* __restrict__ W2, int Nw,
    float* __restrict__ o0, float* __restrict__ o1)
{
    __shared__ __half As[2][128][40];
    __shared__ __half Bs[2][32][136];

    int tid = threadIdx.x;
    int warp = tid >> 5, lane = tid & 31;
    int bm = blockIdx.y * 128;
    int bn = blockIdx.x * 128;
    int wm = (warp >> 2) * 64;
    int wn = (warp & 3) * 32;

    float acc[4][4][4];
#pragma unroll
    for (int mi = 0; mi < 4; mi++)
#pragma unroll
        for (int ni = 0; ni < 4; ni++)
#pragma unroll
            for (int r = 0; r < 4; r++) acc[mi][ni][r] = 0.0f;

    int arow0 = tid >> 2;            // 0..63
    int acol0 = (tid & 3) * 8;       // 0,8,16,24
    int brow0 = tid >> 4;            // 0..15
    int bcol0 = (tid & 15) * 8;      // 0..120

    const int kiter = 1536 / 32;     // 48
    uint4 ra0, ra1, rb0, rb1;

    {
        ra0 = *(const uint4*)&A0[(size_t)(bm + arow0) * HD + acol0];
        ra1 = *(const uint4*)&A0[(size_t)(bm + 64 + arow0) * HD + acol0];
        rb0 = *(const uint4*)&W2[(size_t)brow0 * Nw + bn + bcol0];
        rb1 = *(const uint4*)&W2[(size_t)(16 + brow0) * Nw + bn + bcol0];
        *(uint4*)&As[0][arow0][acol0]      = ra0;
        *(uint4*)&As[0][64 + arow0][acol0] = ra1;
        *(uint4*)&Bs[0][brow0][bcol0]      = rb0;
        *(uint4*)&Bs[0][16 + brow0][bcol0] = rb1;
    }
    __syncthreads();

    int cur = 0;
    for (int it = 0; it < kiter; it++) {
        if (it + 1 < kiter) {
            int kk0 = (it + 1) * 32;
            const __half* Asrc = (kk0 >= 1024) ? A1 : A0;
            int scol = kk0 & 511;
            ra0 = *(const uint4*)&Asrc[(size_t)(bm + arow0) * HD + scol + acol0];
            ra1 = *(const uint4*)&Asrc[(size_t)(bm + 64 + arow0) * HD + scol + acol0];
            rb0 = *(const uint4*)&W2[(size_t)(kk0 + brow0) * Nw + bn + bcol0];
            rb1 = *(const uint4*)&W2[(size_t)(kk0 + 16 + brow0) * Nw + bn + bcol0];
        }
#pragma unroll
        for (int ks = 0; ks < 32; ks += 16) {
            uint32_t af[4][4], bfr[4][2];
#pragma unroll
            for (int mi = 0; mi < 4; mi++) {
                uint32_t addr = (uint32_t)__cvta_generic_to_shared(
                    &As[cur][wm + mi * 16 + (lane & 15)][ks + ((lane >> 4) << 3)]);
                asm volatile("ldmatrix.sync.aligned.m8n8.x4.shared.b16 {%0,%1,%2,%3}, [%4];\n"
                             : "=r"(af[mi][0]), "=r"(af[mi][1]), "=r"(af[mi][2]), "=r"(af[mi][3])
                             : "r"(addr));
            }
#pragma unroll
            for (int ni = 0; ni < 4; ni++) {
                uint32_t addr = (uint32_t)__cvta_generic_to_shared(
                    &Bs[cur][ks + (lane & 15)][wn + ni * 8]);
                asm volatile("ldmatrix.sync.aligned.m8n8.x2.trans.shared.b16 {%0,%1}, [%2];\n"
                             : "=r"(bfr[ni][0]), "=r"(bfr[ni][1]) : "r"(addr));
            }
#pragma unroll
            for (int mi = 0; mi < 4; mi++)
#pragma unroll
                for (int ni = 0; ni < 4; ni++) {
                    asm volatile(
                        "mma.sync.aligned.m16n8k16.row.col.f32.f16.f16.f32 "
                        "{%0,%1,%2,%3}, {%4,%5,%6,%7}, {%8,%9}, {%0,%1,%2,%3};\n"
                        : "+f"(acc[mi][ni][0]), "+f"(acc[mi][ni][1]),
                          "+f"(acc[mi][ni][2]), "+f"(acc[mi][ni][3])
                        : "r"(af[mi][0]), "r"(af[mi][1]), "r"(af[mi][2]), "r"(af[mi][3]),
                          "r"(bfr[ni][0]), "r"(bfr[ni][1]));
                }
        }
        if (it + 1 < kiter) {
            int nb = cur ^ 1;
            *(uint4*)&As[nb][arow0][acol0]      = ra0;
            *(uint4*)&As[nb][64 + arow0][acol0] = ra1;
            *(uint4*)&Bs[nb][brow0][bcol0]      = rb0;
            *(uint4*)&Bs[nb][16 + brow0][bcol0] = rb1;
            __syncthreads();
            cur ^= 1;
        }
    }

    float* O = (bn >= 512) ? o1 : o0;
    int nb0 = bn & 511;
#pragma unroll
    for (int mi = 0; mi < 4; mi++) {
        int r = bm + wm + mi * 16 + (lane >> 2);
#pragma unroll
        for (int ni = 0; ni < 4; ni++) {
            int c = nb0 + wn + ni * 8 + ((lane & 3) << 1);
            float2 v0 = make_float2(acc[mi][ni][0], acc[mi][ni][1]);
            float2 v1 = make_float2(acc[mi][ni][2], acc[mi][ni][3]);
            *(float2*)&O[(size_t)r * HD + c] = v0;
            *(float2*)&O[(size_t)(r + 8) * HD + c] = v1;
        }
    }
}

// ---------------- v mean over L per (b,h,d) ----------------
__global__ __launch_bounds__(256) void vmean_part_kernel() {
    int bh = blockIdx.x & 31, part = blockIdx.x >> 5;
    int b = bh >> 3, h = bh & 7;
    int t = threadIdx.x;
    int d = t & 63, sub = t >> 6;
    const float* base = g_V + (size_t)b * L * HD + h * D + d;
    float s = 0.0f;
    int lend = (part + 1) * 512;
    for (int l = part * 512 + sub; l < lend; l += 4) s += base[(size_t)l * HD];
    __shared__ float sm[256];
    sm[t] = s;
    __syncthreads();
    if (t < 64)
        g_vmeanpart[(bh * 8 + part) * D + t] = sm[t] + sm[t + 64] + sm[t + 128] + sm[t + 192];
}

__global__ __launch_bounds__(256) void vmean_reduce_kernel() {
    int i = blockIdx.x * 256 + threadIdx.x;
    if (i >= BH * D) return;
    int bh = i >> 6, d = i & 63;
    float s = 0.0f;
#pragma unroll
    for (int p = 0; p < 8; p++) s += g_vmeanpart[(bh * 8 + p) * D + d];
    g_vmean[i] = s * (1.0f / (float)L);
}

// ---------------- M[b,h,l] = max_s(qk) - mean_s(qk) ----------------
__global__ __launch_bounds__(256) void compute_M_kernel(const int* __restrict__ idx) {
    int bl = blockIdx.x;
    int b = bl >> 12;
    int l = bl & (L - 1);
    int h = threadIdx.x >> 5;
    int lane = threadIdx.x & 31;
    int half = lane >> 4, sl = lane & 15;

    __shared__ int sidx[S];
    if (threadIdx.x < S) sidx[threadIdx.x] = idx[l * S + threadIdx.x];
    __syncthreads();

    float4 q = *(const float4*)(g_Q + (size_t)bl * HD + h * D + sl * 4);

    float mx = -FLT_MAX, sum = 0.0f;
#pragma unroll 1
    for (int t = 0; t < 23; t++) {
        int s = 2 * t + half;
        bool ok = (s < S);
        int j = sidx[ok ? s : 0];
        float4 kk = *(const float4*)(g_K + ((size_t)b * L + j) * HD + h * D + sl * 4);
        float p = q.x * kk.x + q.y * kk.y + q.z * kk.z + q.w * kk.w;
#pragma unroll
        for (int o = 1; o < 16; o <<= 1) p += __shfl_xor_sync(0xffffffffu, p, o);
        if (ok) { mx = fmaxf(mx, p); sum += p; }
    }
    float mxo  = __shfl_xor_sync(0xffffffffu, mx, 16);
    float sumo = __shfl_xor_sync(0xffffffffu, sum, 16);
    mx = fmaxf(mx, mxo);
    sum += sumo;
    if (lane == 0)
        g_M[((size_t)b * H + h) * L + l] = mx - sum * (1.0f / (float)S);
}

// ---------------- top-45 per (b,h), lowest-index tie-break ----------------
__global__ __launch_bounds__(256) void topk_kernel() {
    int bh = blockIdx.x;
    __shared__ float sv[L];
    __shared__ float rv[256];
    __shared__ int   ri[256];
    int t = threadIdx.x;
    const float* Mrow = g_M + (size_t)bh * L;
    for (int i = t; i < L; i += 256) sv[i] = Mrow[i];
    __syncthreads();
    for (int u = 0; u < U; u++) {
        float best = -FLT_MAX;
        int bi = L;
        for (int i = t; i < L; i += 256) {
            float v = sv[i];
            if (v > best) { best = v; bi = i; }
        }
        rv[t] = best; ri[t] = bi;
        __syncthreads();
        for (int s = 128; s; s >>= 1) {
            if (t < s) {
                if (rv[t + s] > rv[t] || (rv[t + s] == rv[t] && ri[t + s] < ri[t])) {
                    rv[t] = rv[t + s]; ri[t] = ri[t + s];
                }
            }
            __syncthreads();
        }
        if (t == 0) {
            g_topidx[bh * U + u] = ri[0];
            sv[ri[0]] = -FLT_MAX;
        }
        __syncthreads();
    }
}

// ---------------- fused scores+softmax+PV (flash-style, per L-chunk) ----------------
__global__ __launch_bounds__(256) void attn_fused_kernel() {
    extern __shared__ float fs[];
    float* Qs   = fs;                    // 48 x FST
    float* Ks   = Qs + 48 * FST;         // 64 x FST
    float* Vs   = Ks + 64 * FST;         // 64 x FST
    float* Ss   = Vs + 64 * FST;         // 48 x FST
    float* m_sh = Ss + 48 * FST;         // 48
    float* s_sh = m_sh + 48;             // 48
    float* r_sh = s_sh + 48;             // 48

    int chunk = blockIdx.x, bh = blockIdx.y;
    int b = bh >> 3, h = bh & 7;
    int t = threadIdx.x;
    int d = t & 63, ug = t >> 6;
    int l0g = chunk * (L / FCH);

    for (int i = t; i < U * 16; i += 256) {
        int u = i >> 4, c4 = (i & 15) * 4;
        int li = g_topidx[bh * U + u];
        float4 q = *(const float4*)&g_Q[((size_t)b * L + li) * HD + h * D + c4];
        Qs[u * FST + c4 + 0] = q.x;
        Qs[u * FST + c4 + 1] = q.y;
        Qs[u * FST + c4 + 2] = q.z;
        Qs[u * FST + c4 + 3] = q.w;
    }
    if (t < 48) { m_sh[t] = -FLT_MAX; s_sh[t] = 0.0f; }

    float acc[12];
#pragma unroll
    for (int r = 0; r < 12; r++) acc[r] = 0.0f;
    __syncthreads();

    for (int sub = 0; sub < 8; sub++) {
        for (int i = t; i < 64 * 16; i += 256) {
            int r = i >> 4, c4 = (i & 15) * 4;
            size_t base = ((size_t)b * L + l0g + sub * 64 + r) * HD + h * D + c4;
            float4 kk = *(const float4*)&g_K[base];
            Ks[r * FST + c4 + 0] = kk.x; Ks[r * FST + c4 + 1] = kk.y;
            Ks[r * FST + c4 + 2] = kk.z; Ks[r * FST + c4 + 3] = kk.w;
            float4 vv = *(const float4*)&g_V[base];
            Vs[r * FST + c4 + 0] = vv.x; Vs[r * FST + c4 + 1] = vv.y;
            Vs[r * FST + c4 + 2] = vv.z; Vs[r * FST + c4 + 3] = vv.w;
        }
        __syncthreads();

        if (t < 192) {
            int u0 = (t >> 4) * 4, ll0 = (t & 15) * 4;
            float sa[4][4];
#pragma unroll
            for (int j = 0; j < 4; j++)
#pragma unroll
                for (int jj = 0; jj < 4; jj++) sa[j][jj] = 0.0f;
            for (int dd = 0; dd < 64; dd++) {
                float qv[4], kv[4];
#pragma unroll
                for (int j = 0; j < 4; j++) qv[j] = Qs[(u0 + j) * FST + dd];
#pragma unroll
                for (int j = 0; j < 4; j++) kv[j] = Ks[(ll0 + j) * FST + dd];
#pragma unroll
                for (int j = 0; j < 4; j++)
#pragma unroll
                    for (int jj = 0; jj < 4; jj++) sa[j][jj] += qv[j] * kv[jj];
            }
#pragma unroll
            for (int j = 0; j < 4; j++)
#pragma unroll
                for (int jj = 0; jj < 4; jj++)
                    Ss[(u0 + j) * FST + ll0 + jj] = sa[j][jj] * 0.125f;
        }
        __syncthreads();

        if (t < U) {
            float* row = Ss + t * FST;
            float tm = row[0];
            for (int l = 1; l < 64; l++) tm = fmaxf(tm, row[l]);
            float om = m_sh[t];
            float nm = fmaxf(om, tm);
            float rs = __expf(om - nm);
            float se = 0.0f;
            for (int l = 0; l < 64; l++) {
                float e = __expf(row[l] - nm);
                row[l] = e;
                se += e;
            }
            m_sh[t] = nm;
            s_sh[t] = s_sh[t] * rs + se;
            r_sh[t] = rs;
        }
        __syncthreads();

#pragma unroll
        for (int r = 0; r < 12; r++) {
            int u = ug + 4 * r;
            if (u < U) {
                float a = acc[r] * r_sh[u];
                const float* e = Ss + u * FST;
#pragma unroll 8
                for (int l = 0; l < 64; l++) a += e[l] * Vs[l * FST + d];
                acc[r] = a;
            }
        }
        __syncthreads();
    }

#pragma unroll
    for (int r = 0; r < 12; r++) {
        int u = ug + 4 * r;
        if (u < U)
            g_ctxpart[((size_t)bh * FCH + chunk) * (U * D) + u * D + d] = acc[r];
    }
    if (t < U) {
        g_pm[(bh * FCH + chunk) * U + t] = m_sh[t];
        g_ps[(bh * FCH + chunk) * U + t] = s_sh[t];
    }
}

// ---------------- LSE merge across chunks ----------------
__global__ __launch_bounds__(256) void attn_merge_kernel() {
    int i = blockIdx.x * 256 + threadIdx.x;
    if (i >= BH * U * D) return;
    int bh = i / (U * D);
    int rem = i % (U * D);
    int u = rem / D;
    float gm = -FLT_MAX;
#pragma unroll
    for (int c = 0; c < FCH; c++)
        gm = fmaxf(gm, g_pm[(bh * FCH + c) * U + u]);
    float den = 0.0f, num = 0.0f;
#pragma unroll
    for (int c = 0; c < FCH; c++) {
        float w = __expf(g_pm[(bh * FCH + c) * U + u] - gm);
        den += g_ps[(bh * FCH + c) * U + u] * w;
        num += g_ctxpart[((size_t)bh * FCH + c) * (U * D) + rem] * w;
    }
    g_ctxsel[i] = num / den;
}

// ---------------- context (fp16 hi/lo) ----------------
__global__ __launch_bounds__(256) void fill_context_kernel() {
    size_t e = (size_t)blockIdx.x * 256 + threadIdx.x;
    int col = (int)(e & (HD - 1));
    size_t bl = e >> 9;
    int b = (int)(bl >> 12);
    int h = col >> 6, d = col & 63;
    float v = g_vmean[(b * H + h) * D + d];
    __half hh = __float2half_rn(v);
    g_c0[e] = hh;
    g_c1[e] = __float2half_rn(v - __half2float(hh));
}

__global__ __launch_bounds__(64) void scatter_kernel() {
    int bhu = blockIdx.x;
    int d = threadIdx.x;
    int bh = bhu / U, u = bhu % U;
    int b = bh >> 3, h = bh & 7;
    int li = g_topidx[bh * U + u];
    float v = g_ctxsel[(size_t)bhu * D + d];
    __half hh = __float2half_rn(v);
    size_t e = ((size_t)b * L + li) * HD + h * D + d;
    g_c0[e] = hh;
    g_c1[e] = __float2half_rn(v - __half2float(hh));
}

// ---------------- launch ----------------
extern "C" void kernel_launch(void* const* d_in, const int* in_sizes, int n_in,
                              void* d_out, int out_size) {
    const float* x  = (const float*)d_in[0];
    const float* Wq = (const float*)d_in[1];
    const float* Wk = (const float*)d_in[2];
    const float* Wv = (const float*)d_in[3];
    const float* Wo = (const float*)d_in[4];
    const int*   idx = (const int*)d_in[5];
    float* out = (float*)d_out;

    __half *x0, *x1, *W2qk, *W2v, *W2o, *c0, *c1;
    float *Q, *K, *V;
    cudaGetSymbolAddress((void**)&x0, g_x0);
    cudaGetSymbolAddress((void**)&x1, g_x1);
    cudaGetSymbolAddress((void**)&W2qk, g_W2qk);
    cudaGetSymbolAddress((void**)&W2v,  g_W2v);
    cudaGetSymbolAddress((void**)&W2o,  g_W2o);
    cudaGetSymbolAddress((void**)&c0, g_c0);
    cudaGetSymbolAddress((void**)&c1, g_c1);
    cudaGetSymbolAddress((void**)&Q, g_Q);
    cudaGetSymbolAddress((void**)&K, g_K);
    cudaGetSymbolAddress((void**)&V, g_V);

    const int FSMEM = (48 * FST + 64 * FST + 64 * FST + 48 * FST + 144) * 4;
    cudaFuncSetAttribute(attn_fused_kernel, cudaFuncAttributeMaxDynamicSharedMemorySize, FSMEM);

    split_x_kernel<<<(BL * HD) / 1024, 256>>>(x);
    build_w2_kernel<<<1024, 256>>>(Wq, W2qk, 1024, 0);
    build_w2_kernel<<<1024, 256>>>(Wk, W2qk, 1024, 512);
    build_w2_kernel<<<1024, 256>>>(Wv, W2v, 512, 0);
    build_w2_kernel<<<1024, 256>>>(Wo, W2o, 512, 0);

    // Q,K projection (N=1024 -> Q cols then K cols), Ktot=1536
    gemm_f16<<<dim3(8, 128), 256>>>(x0, x1, W2qk, 1024, Q, K);
    // V projection
    gemm_f16<<<dim3(4, 128), 256>>>(x0, x1, W2v, 512, V, V);

    vmean_part_kernel<<<256, 256>>>();
    vmean_reduce_kernel<<<8, 256>>>();
    compute_M_kernel<<<BL, 256>>>(idx);
    topk_kernel<<<BH, 256>>>();

    attn_fused_kernel<<<dim3(FCH, BH), 256, FSMEM>>>();
    attn_merge_kernel<<<(BH * U * D + 255) / 256, 256>>>();

    fill_context_kernel<<<(BL * HD) / 256, 256>>>();
    scatter_kernel<<<BH * U, 64>>>();

    // output projection on context hi/lo
    gemm_f16<<<dim3(4, 128), 256>>>(c0, c1, W2o, 512, out, out);
}

// round 12
// speedup vs baseline: 1.4829x; 1.0329x over previous
#include <cuda_runtime.h>
#include <cuda_fp16.h>
#include <float.h>
#include <stdint.h>

// Problem constants
#define B   4
#define L   4096
#define HD  512
#define H   8
#define D   64
#define S   45
#define U   45
#define BL  (B * L)            // 16384
#define BH  (B * H)            // 32
#define FCH 8                  // L-chunks for fused attention
#define FST 65                 // smem row stride (floats)

// GEMM cp.async pipeline
#define NSTG 4
#define A_HW (128 * 40)        // 5120 halfwords per A stage
#define B_HW (32 * 136)        // 4352 halfwords per B stage
#define ST_HW (A_HW + B_HW)    // 9472
#define GSMEM (NSTG * ST_HW * 2)   // 75776 bytes

// ---------------- device scratch (static; no runtime allocation) ----------------
__device__ __half g_x0[BL * HD];
__device__ __half g_x1[BL * HD];
__device__ __half g_W2qk[1536 * 1024];   // [Ktot=1536][N=1024] stacked [Wq|Wk]
__device__ __half g_W2v[1536 * 512];     // [Ktot=1536][N=512]
__device__ float g_Q[BL * HD];
__device__ float g_K[BL * HD];
__device__ float g_V[BL * HD];
__device__ float g_M[BH * L];
__device__ int   g_topidx[BH * U];
__device__ float g_vmeanpart[BH * 8 * D];
__device__ float g_vmean[BH * D];
__device__ float g_ctxpart[BH * FCH * U * D];
__device__ float g_pm[BH * FCH * U];
__device__ float g_ps[BH * FCH * U];
__device__ float g_ctxsel[BH * U * D];
__device__ float g_bop[B * 8 * HD];      // base_out split-K partials
__device__ float g_baseout[B * HD];      // vmean-concat @ Wo per batch
__device__ int   g_slot[BL * H];         // selecting u per (row,h), -1 = none

static __device__ __forceinline__ unsigned short h16u(__half v) {
    return *(unsigned short*)&v;
}
__device__ __forceinline__ uint32_t smem_u32(const void* p) {
    uint32_t a;
    asm("{ .reg .u64 t; cvta.to.shared.u64 t, %1; cvt.u32.u64 %0, t; }" : "=r"(a) : "l"(p));
    return a;
}
__device__ __forceinline__ void cp16(uint32_t dst, const void* src) {
    asm volatile("cp.async.cg.shared.global [%0], [%1], 16;" :: "r"(dst), "l"(src));
}

// ---------------- split x into 2 fp16 residual levels ----------------
__global__ __launch_bounds__(256) void split_x_kernel(const float* __restrict__ x) {
    size_t i = ((size_t)blockIdx.x * 256 + threadIdx.x) * 4;
    float4 v = *(const float4*)(x + i);
    float vv[4] = {v.x, v.y, v.z, v.w};
    unsigned short h0[4], h1[4];
#pragma unroll
    for (int j = 0; j < 4; j++) {
        __half a0 = __float2half_rn(vv[j]);
        __half a1 = __float2half_rn(vv[j] - __half2float(a0));
        h0[j] = h16u(a0); h1[j] = h16u(a1);
    }
    uint2 p;
    p.x = h0[0] | ((uint32_t)h0[1] << 16); p.y = h0[2] | ((uint32_t)h0[3] << 16);
    *(uint2*)&g_x0[i] = p;
    p.x = h1[0] | ((uint32_t)h1[1] << 16); p.y = h1[2] | ((uint32_t)h1[3] << 16);
    *(uint2*)&g_x1[i] = p;
}

// ---------------- build stacked split-W [Ktot=1536][N]; sections {w0,w1,w0} ----------------
__global__ __launch_bounds__(256) void build_w2_kernel(const float* __restrict__ W,
                                                       __half* __restrict__ out,
                                                       int outW, int colOff) {
    int id = blockIdx.x * 256 + threadIdx.x;   // < 512*512
    int r = id >> 9, c = id & 511;
    float v = W[id];
    __half b0 = __float2half_rn(v);
    __half b1 = __float2half_rn(v - __half2float(b0));
    out[(size_t)r * outW + colOff + c] = b0;
    out[(size_t)(512 + r) * outW + colOff + c] = b1;
    out[(size_t)(1024 + r) * outW + colOff + c] = b0;
}

// ---------------- fp16 split GEMM, cp.async 4-stage, Ktot=1536 ----------------
// C = x0@W0 + x0@W1 + x1@W0.  A sections {0,0,1}.  128x128 tile, BK=32,
// 8 warps in 2x4 (64x32 warp tiles).
__global__ __launch_bounds__(256, 2) void gemm_f16(
    const __half* __restrict__ A0, const __half* __restrict__ A1,
    const __half* __restrict__ W2, int Nw,
    float* __restrict__ o0, float* __restrict__ o1)
{
    extern __shared__ __half sh[];
    int tid = threadIdx.x;
    int warp = tid >> 5, lane = tid & 31;
    int bm = blockIdx.y * 128;
    int bn = blockIdx.x * 128;
    int wm = (warp >> 2) * 64;
    int wn = (warp & 3) * 32;

    float acc[4][4][4];
#pragma unroll
    for (int mi = 0; mi < 4; mi++)
#pragma unroll
        for (int ni = 0; ni < 4; ni++)
#pragma unroll
            for (int r = 0; r < 4; r++) acc[mi][ni][r] = 0.0f;

    const int kiter = 1536 / 32;   // 48

    auto ld = [&](int it) {
        int st = it & (NSTG - 1);
        __half* Ab = sh + st * ST_HW;
        __half* Bb = Ab + A_HW;
        int kk0 = it * 32;
        const __half* Asrc = (kk0 >= 1024) ? A1 : A0;
        int scol = kk0 & 511;
#pragma unroll
        for (int j = 0; j < 2; j++) {
            int c = tid * 2 + j;                 // 0..511
            int r = c >> 2, col = (c & 3) * 8;
            cp16(smem_u32(Ab + r * 40 + col),
                 Asrc + (size_t)(bm + r) * HD + scol + col);
        }
#pragma unroll
        for (int j = 0; j < 2; j++) {
            int c = tid * 2 + j;
            int r = c >> 4, col = (c & 15) * 8;
            cp16(smem_u32(Bb + r * 136 + col),
                 W2 + (size_t)(kk0 + r) * Nw + bn + col);
        }
        asm volatile("cp.async.commit_group;" ::: "memory");
    };

    ld(0); ld(1); ld(2);

    for (int it = 0; it < kiter; it++) {
        asm volatile("cp.async.wait_group 2;" ::: "memory");
        __syncthreads();
        if (it + 3 < kiter) ld(it + 3);

        __half* Ab = sh + (it & (NSTG - 1)) * ST_HW;
        __half* Bb = Ab + A_HW;
#pragma unroll
        for (int ks = 0; ks < 32; ks += 16) {
            uint32_t af[4][4], bfr[4][2];
#pragma unroll
            for (int mi = 0; mi < 4; mi++) {
                uint32_t addr = smem_u32(
                    Ab + (wm + mi * 16 + (lane & 15)) * 40 + ks + ((lane >> 4) << 3));
                asm volatile("ldmatrix.sync.aligned.m8n8.x4.shared.b16 {%0,%1,%2,%3}, [%4];\n"
                             : "=r"(af[mi][0]), "=r"(af[mi][1]), "=r"(af[mi][2]), "=r"(af[mi][3])
                             : "r"(addr));
            }
#pragma unroll
            for (int ni = 0; ni < 4; ni++) {
                uint32_t addr = smem_u32(Bb + (ks + (lane & 15)) * 136 + wn + ni * 8);
                asm volatile("ldmatrix.sync.aligned.m8n8.x2.trans.shared.b16 {%0,%1}, [%2];\n"
                             : "=r"(bfr[ni][0]), "=r"(bfr[ni][1]) : "r"(addr));
            }
#pragma unroll
            for (int mi = 0; mi < 4; mi++)
#pragma unroll
                for (int ni = 0; ni < 4; ni++) {
                    asm volatile(
                        "mma.sync.aligned.m16n8k16.row.col.f32.f16.f16.f32 "
                        "{%0,%1,%2,%3}, {%4,%5,%6,%7}, {%8,%9}, {%0,%1,%2,%3};\n"
                        : "+f"(acc[mi][ni][0]), "+f"(acc[mi][ni][1]),
                          "+f"(acc[mi][ni][2]), "+f"(acc[mi][ni][3])
                        : "r"(af[mi][0]), "r"(af[mi][1]), "r"(af[mi][2]), "r"(af[mi][3]),
                          "r"(bfr[ni][0]), "r"(bfr[ni][1]));
                }
        }
        __syncthreads();
    }

    float* O = (bn >= 512) ? o1 : o0;
    int nb0 = bn & 511;
#pragma unroll
    for (int mi = 0; mi < 4; mi++) {
        int r = bm + wm + mi * 16 + (lane >> 2);
#pragma unroll
        for (int ni = 0; ni < 4; ni++) {
            int c = nb0 + wn + ni * 8 + ((lane & 3) << 1);
            float2 v0 = make_float2(acc[mi][ni][0], acc[mi][ni][1]);
            float2 v1 = make_float2(acc[mi][ni][2], acc[mi][ni][3]);
            *(float2*)&O[(size_t)r * HD + c] = v0;
            *(float2*)&O[(size_t)(r + 8) * HD + c] = v1;
        }
    }
}

// ---------------- v mean over L per (b,h,d) ----------------
__global__ __launch_bounds__(256) void vmean_part_kernel() {
    int bh = blockIdx.x & 31, part = blockIdx.x >> 5;
    int b = bh >> 3, h = bh & 7;
    int t = threadIdx.x;
    int d = t & 63, sub = t >> 6;
    const float* base = g_V + (size_t)b * L * HD + h * D + d;
    float s = 0.0f;
    int lend = (part + 1) * 512;
    for (int l = part * 512 + sub; l < lend; l += 4) s += base[(size_t)l * HD];
    __shared__ float sm[256];
    sm[t] = s;
    __syncthreads();
    if (t < 64)
        g_vmeanpart[(bh * 8 + part) * D + t] = sm[t] + sm[t + 64] + sm[t + 128] + sm[t + 192];
}

__global__ __launch_bounds__(256) void vmean_reduce_kernel() {
    int i = blockIdx.x * 256 + threadIdx.x;
    if (i >= BH * D) return;
    int bh = i >> 6, d = i & 63;
    float s = 0.0f;
#pragma unroll
    for (int p = 0; p < 8; p++) s += g_vmeanpart[(bh * 8 + p) * D + d];
    g_vmean[i] = s * (1.0f / (float)L);
}

// ---------------- M[b,h,l] = max_s(qk) - mean_s(qk) ----------------
__global__ __launch_bounds__(256) void compute_M_kernel(const int* __restrict__ idx) {
    int bl = blockIdx.x;
    int b = bl >> 12;
    int l = bl & (L - 1);
    int h = threadIdx.x >> 5;
    int lane = threadIdx.x & 31;
    int half = lane >> 4, sl = lane & 15;

    __shared__ int sidx[S];
    if (threadIdx.x < S) sidx[threadIdx.x] = idx[l * S + threadIdx.x];
    __syncthreads();

    float4 q = *(const float4*)(g_Q + (size_t)bl * HD + h * D + sl * 4);

    float mx = -FLT_MAX, sum = 0.0f;
#pragma unroll 1
    for (int t = 0; t < 23; t++) {
        int s = 2 * t + half;
        bool ok = (s < S);
        int j = sidx[ok ? s : 0];
        float4 kk = *(const float4*)(g_K + ((size_t)b * L + j) * HD + h * D + sl * 4);
        float p = q.x * kk.x + q.y * kk.y + q.z * kk.z + q.w * kk.w;
#pragma unroll
        for (int o = 1; o < 16; o <<= 1) p += __shfl_xor_sync(0xffffffffu, p, o);
        if (ok) { mx = fmaxf(mx, p); sum += p; }
    }
    float mxo  = __shfl_xor_sync(0xffffffffu, mx, 16);
    float sumo = __shfl_xor_sync(0xffffffffu, sum, 16);
    mx = fmaxf(mx, mxo);
    sum += sumo;
    if (lane == 0)
        g_M[((size_t)b * H + h) * L + l] = mx - sum * (1.0f / (float)S);
}

// ---------------- top-45 per (b,h), lowest-index tie-break ----------------
__global__ __launch_bounds__(256) void topk_kernel() {
    int bh = blockIdx.x;
    __shared__ float sv[L];
    __shared__ float rv[256];
    __shared__ int   ri[256];
    int t = threadIdx.x;
    const float* Mrow = g_M + (size_t)bh * L;
    for (int i = t; i < L; i += 256) sv[i] = Mrow[i];
    __syncthreads();
    for (int u = 0; u < U; u++) {
        float best = -FLT_MAX;
        int bi = L;
        for (int i = t; i < L; i += 256) {
            float v = sv[i];
            if (v > best) { best = v; bi = i; }
        }
        rv[t] = best; ri[t] = bi;
        __syncthreads();
        for (int s = 128; s; s >>= 1) {
            if (t < s) {
                if (rv[t + s] > rv[t] || (rv[t + s] == rv[t] && ri[t + s] < ri[t])) {
                    rv[t] = rv[t + s]; ri[t] = ri[t + s];
                }
            }
            __syncthreads();
        }
        if (t == 0) {
            g_topidx[bh * U + u] = ri[0];
            sv[ri[0]] = -FLT_MAX;
        }
        __syncthreads();
    }
}

// ---------------- fused scores+softmax+PV (flash-style, per L-chunk) ----------------
__global__ __launch_bounds__(256) void attn_fused_kernel() {
    extern __shared__ float fs[];
    float* Qs   = fs;                    // 48 x FST
    float* Ks   = Qs + 48 * FST;         // 64 x FST
    float* Vs   = Ks + 64 * FST;         // 64 x FST
    float* Ss   = Vs + 64 * FST;         // 48 x FST
    float* m_sh = Ss + 48 * FST;         // 48
    float* s_sh = m_sh + 48;             // 48
    float* r_sh = s_sh + 48;             // 48

    int chunk = blockIdx.x, bh = blockIdx.y;
    int b = bh >> 3, h = bh & 7;
    int t = threadIdx.x;
    int d = t & 63, ug = t >> 6;
    int l0g = chunk * (L / FCH);

    for (int i = t; i < U * 16; i += 256) {
        int u = i >> 4, c4 = (i & 15) * 4;
        int li = g_topidx[bh * U + u];
        float4 q = *(const float4*)&g_Q[((size_t)b * L + li) * HD + h * D + c4];
        Qs[u * FST + c4 + 0] = q.x;
        Qs[u * FST + c4 + 1] = q.y;
        Qs[u * FST + c4 + 2] = q.z;
        Qs[u * FST + c4 + 3] = q.w;
    }
    if (t < 48) { m_sh[t] = -FLT_MAX; s_sh[t] = 0.0f; }

    float acc[12];
#pragma unroll
    for (int r = 0; r < 12; r++) acc[r] = 0.0f;
    __syncthreads();

    for (int sub = 0; sub < 8; sub++) {
        for (int i = t; i < 64 * 16; i += 256) {
            int r = i >> 4, c4 = (i & 15) * 4;
            size_t base = ((size_t)b * L + l0g + sub * 64 + r) * HD + h * D + c4;
            float4 kk = *(const float4*)&g_K[base];
            Ks[r * FST + c4 + 0] = kk.x; Ks[r * FST + c4 + 1] = kk.y;
            Ks[r * FST + c4 + 2] = kk.z; Ks[r * FST + c4 + 3] = kk.w;
            float4 vv = *(const float4*)&g_V[base];
            Vs[r * FST + c4 + 0] = vv.x; Vs[r * FST + c4 + 1] = vv.y;
            Vs[r * FST + c4 + 2] = vv.z; Vs[r * FST + c4 + 3] = vv.w;
        }
        __syncthreads();

        if (t < 192) {
            int u0 = (t >> 4) * 4, ll0 = (t & 15) * 4;
            float sa[4][4];
#pragma unroll
            for (int j = 0; j < 4; j++)
#pragma unroll
                for (int jj = 0; jj < 4; jj++) sa[j][jj] = 0.0f;
            for (int dd = 0; dd < 64; dd++) {
                float qv[4], kv[4];
#pragma unroll
                for (int j = 0; j < 4; j++) qv[j] = Qs[(u0 + j) * FST + dd];
#pragma unroll
                for (int j = 0; j < 4; j++) kv[j] = Ks[(ll0 + j) * FST + dd];
#pragma unroll
                for (int j = 0; j < 4; j++)
#pragma unroll
                    for (int jj = 0; jj < 4; jj++) sa[j][jj] += qv[j] * kv[jj];
            }
#pragma unroll
            for (int j = 0; j < 4; j++)
#pragma unroll
                for (int jj = 0; jj < 4; jj++)
                    Ss[(u0 + j) * FST + ll0 + jj] = sa[j][jj] * 0.125f;
        }
        __syncthreads();

        if (t < U) {
            float* row = Ss + t * FST;
            float tm = row[0];
            for (int l = 1; l < 64; l++) tm = fmaxf(tm, row[l]);
            float om = m_sh[t];
            float nm = fmaxf(om, tm);
            float rs = __expf(om - nm);
            float se = 0.0f;
            for (int l = 0; l < 64; l++) {
                float e = __expf(row[l] - nm);
                row[l] = e;
                se += e;
            }
            m_sh[t] = nm;
            s_sh[t] = s_sh[t] * rs + se;
            r_sh[t] = rs;
        }
        __syncthreads();

#pragma unroll
        for (int r = 0; r < 12; r++) {
            int u = ug + 4 * r;
            if (u < U) {
                float a = acc[r] * r_sh[u];
                const float* e = Ss + u * FST;
#pragma unroll 8
                for (int l = 0; l < 64; l++) a += e[l] * Vs[l * FST + d];
                acc[r] = a;
            }
        }
        __syncthreads();
    }

#pragma unroll
    for (int r = 0; r < 12; r++) {
        int u = ug + 4 * r;
        if (u < U)
            g_ctxpart[((size_t)bh * FCH + chunk) * (U * D) + u * D + d] = acc[r];
    }
    if (t < U) {
        g_pm[(bh * FCH + chunk) * U + t] = m_sh[t];
        g_ps[(bh * FCH + chunk) * U + t] = s_sh[t];
    }
}

// ---------------- LSE merge across chunks ----------------
__global__ __launch_bounds__(256) void attn_merge_kernel() {
    int i = blockIdx.x * 256 + threadIdx.x;
    if (i >= BH * U * D) return;
    int bh = i / (U * D);
    int rem = i % (U * D);
    int u = rem / D;
    float gm = -FLT_MAX;
#pragma unroll
    for (int c = 0; c < FCH; c++)
        gm = fmaxf(gm, g_pm[(bh * FCH + c) * U + u]);
    float den = 0.0f, num = 0.0f;
#pragma unroll
    for (int c = 0; c < FCH; c++) {
        float w = __expf(g_pm[(bh * FCH + c) * U + u] - gm);
        den += g_ps[(bh * FCH + c) * U + u] * w;
        num += g_ctxpart[((size_t)bh * FCH + c) * (U * D) + rem] * w;
    }
    g_ctxsel[i] = num / den;
}

// ---------------- base_out[b] = concat_h(vmean[b,h]) @ Wo (split-K partials) ----------------
__global__ __launch_bounds__(512) void baseout_part_kernel(const float* __restrict__ Wo) {
    int b = blockIdx.x >> 3, kc = blockIdx.x & 7;
    int n = threadIdx.x;
    float acc = 0.0f;
#pragma unroll 8
    for (int k0 = 0; k0 < 64; k0++) {
        int k = kc * 64 + k0;
        acc += g_vmean[b * 512 + k] * Wo[(size_t)k * 512 + n];
    }
    g_bop[(b * 8 + kc) * 512 + n] = acc;
}

__global__ __launch_bounds__(256) void baseout_reduce_kernel() {
    int i = blockIdx.x * 256 + threadIdx.x;   // < B*512
    int b = i >> 9;
    int n = i & 511;
    float s = 0.0f;
#pragma unroll
    for (int kc = 0; kc < 8; kc++) s += g_bop[(b * 8 + kc) * 512 + n];
    g_baseout[i] = s;
}

// ---------------- broadcast base_out into all output rows ----------------
__global__ __launch_bounds__(256) void fill_out_kernel(float* __restrict__ out) {
    size_t e4 = (size_t)blockIdx.x * 256 + threadIdx.x;   // < BL*128
    int n4 = (int)(e4 & 127);
    size_t bl = e4 >> 7;
    int b = (int)(bl >> 12);
    float4 v = *(const float4*)&g_baseout[b * 512 + n4 * 4];
    *(float4*)&out[e4 * 4] = v;
}

// ---------------- slot table: which u selected row l for head h ----------------
__global__ __launch_bounds__(256) void slot_init_kernel() {
    int i = blockIdx.x * 256 + threadIdx.x;
    if (i < BL * H) g_slot[i] = -1;
}

__global__ __launch_bounds__(256) void slot_set_kernel() {
    int i = blockIdx.x * 256 + threadIdx.x;   // < BH*U
    if (i >= BH * U) return;
    int bh = i / U, u = i % U;
    int b = bh >> 3, h = bh & 7;
    int li = g_topidx[bh * U + u];
    g_slot[(b * L + li) * H + h] = u;
}

// ---------------- per-row correction: out += (ctxsel - vmean) @ Wo_block ----------------
__global__ __launch_bounds__(128) void correct_kernel(const float* __restrict__ Wo,
                                                      float* __restrict__ out) {
    int row = blockIdx.x;              // 0..BL-1
    int b = row >> 12;
    int t = threadIdx.x;
    __shared__ int sl[8];
    __shared__ float delta[64];
    if (t < 8) sl[t] = g_slot[row * 8 + t];
    __syncthreads();
    int any = 0;
#pragma unroll
    for (int h = 0; h < 8; h++) any |= (sl[h] >= 0);
    if (!any) return;

    int c = t * 4;
    float a0 = 0.0f, a1 = 0.0f, a2 = 0.0f, a3 = 0.0f;
    for (int h = 0; h < 8; h++) {
        int u = sl[h];
        if (u >= 0 && t < 64)
            delta[t] = g_ctxsel[((size_t)(b * 8 + h) * U + u) * 64 + t]
                     - g_vmean[(b * 8 + h) * 64 + t];
        __syncthreads();
        if (u >= 0) {
#pragma unroll 8
            for (int d = 0; d < 64; d++) {
                float dv = delta[d];
                float4 w = *(const float4*)&Wo[(size_t)(h * 64 + d) * 512 + c];
                a0 += dv * w.x; a1 += dv * w.y; a2 += dv * w.z; a3 += dv * w.w;
            }
        }
        __syncthreads();
    }
    float4 o = *(float4*)&out[(size_t)row * 512 + c];
    o.x += a0; o.y += a1; o.z += a2; o.w += a3;
    *(float4*)&out[(size_t)row * 512 + c] = o;
}

// ---------------- launch ----------------
extern "C" void kernel_launch(void* const* d_in, const int* in_sizes, int n_in,
                              void* d_out, int out_size) {
    const float* x  = (const float*)d_in[0];
    const float* Wq = (const float*)d_in[1];
    const float* Wk = (const float*)d_in[2];
    const float* Wv = (const float*)d_in[3];
    const float* Wo = (const float*)d_in[4];
    const int*   idx = (const int*)d_in[5];
    float* out = (float*)d_out;

    __half *x0, *x1, *W2qk, *W2v;
    float *Q, *K, *V;
    cudaGetSymbolAddress((void**)&x0, g_x0);
    cudaGetSymbolAddress((void**)&x1, g_x1);
    cudaGetSymbolAddress((void**)&W2qk, g_W2qk);
    cudaGetSymbolAddress((void**)&W2v,  g_W2v);
    cudaGetSymbolAddress((void**)&Q, g_Q);
    cudaGetSymbolAddress((void**)&K, g_K);
    cudaGetSymbolAddress((void**)&V, g_V);

    const int FSMEM = (48 * FST + 64 * FST + 64 * FST + 48 * FST + 144) * 4;
    cudaFuncSetAttribute(attn_fused_kernel, cudaFuncAttributeMaxDynamicSharedMemorySize, FSMEM);
    cudaFuncSetAttribute(gemm_f16, cudaFuncAttributeMaxDynamicSharedMemorySize, GSMEM);

    split_x_kernel<<<(BL * HD) / 1024, 256>>>(x);
    build_w2_kernel<<<1024, 256>>>(Wq, W2qk, 1024, 0);
    build_w2_kernel<<<1024, 256>>>(Wk, W2qk, 1024, 512);
    build_w2_kernel<<<1024, 256>>>(Wv, W2v, 512, 0);

    // Q,K projection (N=1024 -> Q cols then K cols), Ktot=1536
    gemm_f16<<<dim3(8, 128), 256, GSMEM>>>(x0, x1, W2qk, 1024, Q, K);
    // V projection
    gemm_f16<<<dim3(4, 128), 256, GSMEM>>>(x0, x1, W2v, 512, V, V);

    vmean_part_kernel<<<256, 256>>>();
    vmean_reduce_kernel<<<8, 256>>>();
    compute_M_kernel<<<BL, 256>>>(idx);
    topk_kernel<<<BH, 256>>>();

    attn_fused_kernel<<<dim3(FCH, BH), 256, FSMEM>>>();
    attn_merge_kernel<<<(BH * U * D + 255) / 256, 256>>>();

    // O projection replacement: base GEMV + broadcast + per-row corrections
    baseout_part_kernel<<<B * 8, 512>>>(Wo);
    baseout_reduce_kernel<<<(B * HD) / 256, 256>>>();
    fill_out_kernel<<<(BL * 128) / 256, 256>>>(out);
    slot_init_kernel<<<(BL * H) / 256, 256>>>();
    slot_set_kernel<<<(BH * U + 255) / 256, 256>>>();
    correct_kernel<<<BL, 128>>>(Wo, out);
}

// round 13
// speedup vs baseline: 1.7272x; 1.1647x over previous
#include <cuda_runtime.h>
#include <cuda_fp16.h>
#include <float.h>
#include <stdint.h>

// Problem constants
#define B   4
#define L   4096
#define HD  512
#define H   8
#define D   64
#define S   45
#define U   45
#define BL  (B * L)            // 16384
#define BH  (B * H)            // 32
#define FCH 8                  // L-chunks for fused attention
#define FST 65                 // smem row stride (floats)

// ---------------- device scratch (static; no runtime allocation) ----------------
__device__ __half g_x0[BL * HD];
__device__ __half g_x1[BL * HD];
__device__ __half g_W2qk[1536 * 1024];   // [Ktot=1536][N=1024] stacked [Wq|Wk]
__device__ __half g_W2v[1536 * 512];     // [Ktot=1536][N=512]
__device__ float g_Q[BL * HD];
__device__ float g_K[BL * HD];
__device__ float g_V[BL * HD];
__device__ float g_M[BH * L];
__device__ int   g_topidx[BH * U];
__device__ float g_vmeanpart[BH * 8 * D];
__device__ float g_vmean[BH * D];
__device__ float g_ctxpart[BH * FCH * U * D];
__device__ float g_pm[BH * FCH * U];
__device__ float g_ps[BH * FCH * U];
__device__ float g_ctxsel[BH * U * D];
__device__ float g_bop[B * 8 * HD];      // base_out split-K partials
__device__ float g_baseout[B * HD];      // vmean-concat @ Wo per batch
__device__ int   g_slot[BL * H];         // selecting u per (row,h), -1 = none

static __device__ __forceinline__ unsigned short h16u(__half v) {
    return *(unsigned short*)&v;
}

// ---------------- split x into 2 fp16 residual levels ----------------
__global__ __launch_bounds__(256) void split_x_kernel(const float* __restrict__ x) {
    size_t i = ((size_t)blockIdx.x * 256 + threadIdx.x) * 4;
    float4 v = *(const float4*)(x + i);
    float vv[4] = {v.x, v.y, v.z, v.w};
    unsigned short h0[4], h1[4];
#pragma unroll
    for (int j = 0; j < 4; j++) {
        __half a0 = __float2half_rn(vv[j]);
        __half a1 = __float2half_rn(vv[j] - __half2float(a0));
        h0[j] = h16u(a0); h1[j] = h16u(a1);
    }
    uint2 p;
    p.x = h0[0] | ((uint32_t)h0[1] << 16); p.y = h0[2] | ((uint32_t)h0[3] << 16);
    *(uint2*)&g_x0[i] = p;
    p.x = h1[0] | ((uint32_t)h1[1] << 16); p.y = h1[2] | ((uint32_t)h1[3] << 16);
    *(uint2*)&g_x1[i] = p;
}

// ---------------- build stacked split-W [Ktot=1536][N]; sections {w0,w1,w0} ----------------
__global__ __launch_bounds__(256) void build_w2_kernel(const float* __restrict__ W,
                                                       __half* __restrict__ out,
                                                       int outW, int colOff) {
    int id = blockIdx.x * 256 + threadIdx.x;   // < 512*512
    int r = id >> 9, c = id & 511;
    float v = W[id];
    __half b0 = __float2half_rn(v);
    __half b1 = __float2half_rn(v - __half2float(b0));
    out[(size_t)r * outW + colOff + c] = b0;
    out[(size_t)(512 + r) * outW + colOff + c] = b1;
    out[(size_t)(1024 + r) * outW + colOff + c] = b0;
}

// ---------------- fp16 split GEMM via mma.sync (R11-proven: register-staged) ----------------
// C = x0@W0 + x0@W1 + x1@W0 over stacked Ktot=1536.  A sections {0,0,1}.
// 128x128 tile, BK=32, 8 warps in 2x4 (64x32 warp tiles), double-buffered smem.
__global__ __launch_bounds__(256) void gemm_f16(
    const __half* __restrict__ A0, const __half* __restrict__ A1,
    const __half* __restrict__ W2, int Nw,
    float* __restrict__ o0, float* __restrict__ o1)
{
    __shared__ __half As[2][128][40];
    __shared__ __half Bs[2][32][136];

    int tid = threadIdx.x;
    int warp = tid >> 5, lane = tid & 31;
    int bm = blockIdx.y * 128;
    int bn = blockIdx.x * 128;
    int wm = (warp >> 2) * 64;
    int wn = (warp & 3) * 32;

    float acc[4][4][4];
#pragma unroll
    for (int mi = 0; mi < 4; mi++)
#pragma unroll
        for (int ni = 0; ni < 4; ni++)
#pragma unroll
            for (int r = 0; r < 4; r++) acc[mi][ni][r] = 0.0f;

    int arow0 = tid >> 2;            // 0..63
    int acol0 = (tid & 3) * 8;       // 0,8,16,24
    int brow0 = tid >> 4;            // 0..15
    int bcol0 = (tid & 15) * 8;      // 0..120

    const int kiter = 1536 / 32;     // 48
    uint4 ra0, ra1, rb0, rb1;

    {
        ra0 = *(const uint4*)&A0[(size_t)(bm + arow0) * HD + acol0];
        ra1 = *(const uint4*)&A0[(size_t)(bm + 64 + arow0) * HD + acol0];
        rb0 = *(const uint4*)&W2[(size_t)brow0 * Nw + bn + bcol0];
        rb1 = *(const uint4*)&W2[(size_t)(16 + brow0) * Nw + bn + bcol0];
        *(uint4*)&As[0][arow0][acol0]      = ra0;
        *(uint4*)&As[0][64 + arow0][acol0] = ra1;
        *(uint4*)&Bs[0][brow0][bcol0]      = rb0;
        *(uint4*)&Bs[0][16 + brow0][bcol0] = rb1;
    }
    __syncthreads();

    int cur = 0;
    for (int it = 0; it < kiter; it++) {
        if (it + 1 < kiter) {
            int kk0 = (it + 1) * 32;
            const __half* Asrc = (kk0 >= 1024) ? A1 : A0;
            int scol = kk0 & 511;
            ra0 = *(const uint4*)&Asrc[(size_t)(bm + arow0) * HD + scol + acol0];
            ra1 = *(const uint4*)&Asrc[(size_t)(bm + 64 + arow0) * HD + scol + acol0];
            rb0 = *(const uint4*)&W2[(size_t)(kk0 + brow0) * Nw + bn + bcol0];
            rb1 = *(const uint4*)&W2[(size_t)(kk0 + 16 + brow0) * Nw + bn + bcol0];
        }
#pragma unroll
        for (int ks = 0; ks < 32; ks += 16) {
            uint32_t af[4][4], bfr[4][2];
#pragma unroll
            for (int mi = 0; mi < 4; mi++) {
                uint32_t addr = (uint32_t)__cvta_generic_to_shared(
                    &As[cur][wm + mi * 16 + (lane & 15)][ks + ((lane >> 4) << 3)]);
                asm volatile("ldmatrix.sync.aligned.m8n8.x4.shared.b16 {%0,%1,%2,%3}, [%4];\n"
                             : "=r"(af[mi][0]), "=r"(af[mi][1]), "=r"(af[mi][2]), "=r"(af[mi][3])
                             : "r"(addr));
            }
#pragma unroll
            for (int ni = 0; ni < 4; ni++) {
                uint32_t addr = (uint32_t)__cvta_generic_to_shared(
                    &Bs[cur][ks + (lane & 15)][wn + ni * 8]);
                asm volatile("ldmatrix.sync.aligned.m8n8.x2.trans.shared.b16 {%0,%1}, [%2];\n"
                             : "=r"(bfr[ni][0]), "=r"(bfr[ni][1]) : "r"(addr));
            }
#pragma unroll
            for (int mi = 0; mi < 4; mi++)
#pragma unroll
                for (int ni = 0; ni < 4; ni++) {
                    asm volatile(
                        "mma.sync.aligned.m16n8k16.row.col.f32.f16.f16.f32 "
                        "{%0,%1,%2,%3}, {%4,%5,%6,%7}, {%8,%9}, {%0,%1,%2,%3};\n"
                        : "+f"(acc[mi][ni][0]), "+f"(acc[mi][ni][1]),
                          "+f"(acc[mi][ni][2]), "+f"(acc[mi][ni][3])
                        : "r"(af[mi][0]), "r"(af[mi][1]), "r"(af[mi][2]), "r"(af[mi][3]),
                          "r"(bfr[ni][0]), "r"(bfr[ni][1]));
                }
        }
        if (it + 1 < kiter) {
            int nb = cur ^ 1;
            *(uint4*)&As[nb][arow0][acol0]      = ra0;
            *(uint4*)&As[nb][64 + arow0][acol0] = ra1;
            *(uint4*)&Bs[nb][brow0][bcol0]      = rb0;
            *(uint4*)&Bs[nb][16 + brow0][bcol0] = rb1;
            __syncthreads();
            cur ^= 1;
        }
    }

    float* O = (bn >= 512) ? o1 : o0;
    int nb0 = bn & 511;
#pragma unroll
    for (int mi = 0; mi < 4; mi++) {
        int r = bm + wm + mi * 16 + (lane >> 2);
#pragma unroll
        for (int ni = 0; ni < 4; ni++) {
            int c = nb0 + wn + ni * 8 + ((lane & 3) << 1);
            float2 v0 = make_float2(acc[mi][ni][0], acc[mi][ni][1]);
            float2 v1 = make_float2(acc[mi][ni][2], acc[mi][ni][3]);
            *(float2*)&O[(size_t)r * HD + c] = v0;
            *(float2*)&O[(size_t)(r + 8) * HD + c] = v1;
        }
    }
}

// ---------------- v mean over L per (b,h,d) ----------------
__global__ __launch_bounds__(256) void vmean_part_kernel() {
    int bh = blockIdx.x & 31, part = blockIdx.x >> 5;
    int b = bh >> 3, h = bh & 7;
    int t = threadIdx.x;
    int d = t & 63, sub = t >> 6;
    const float* base = g_V + (size_t)b * L * HD + h * D + d;
    float s = 0.0f;
    int lend = (part + 1) * 512;
    for (int l = part * 512 + sub; l < lend; l += 4) s += base[(size_t)l * HD];
    __shared__ float sm[256];
    sm[t] = s;
    __syncthreads();
    if (t < 64)
        g_vmeanpart[(bh * 8 + part) * D + t] = sm[t] + sm[t + 64] + sm[t + 128] + sm[t + 192];
}

__global__ __launch_bounds__(256) void vmean_reduce_kernel() {
    int i = blockIdx.x * 256 + threadIdx.x;
    if (i >= BH * D) return;
    int bh = i >> 6, d = i & 63;
    float s = 0.0f;
#pragma unroll
    for (int p = 0; p < 8; p++) s += g_vmeanpart[(bh * 8 + p) * D + d];
    g_vmean[i] = s * (1.0f / (float)L);
}

// ---------------- M[b,h,l] = max_s(qk) - mean_s(qk) ----------------
__global__ __launch_bounds__(256) void compute_M_kernel(const int* __restrict__ idx) {
    int bl = blockIdx.x;
    int b = bl >> 12;
    int l = bl & (L - 1);
    int h = threadIdx.x >> 5;
    int lane = threadIdx.x & 31;
    int half = lane >> 4, sl = lane & 15;

    __shared__ int sidx[S];
    if (threadIdx.x < S) sidx[threadIdx.x] = idx[l * S + threadIdx.x];
    __syncthreads();

    float4 q = *(const float4*)(g_Q + (size_t)bl * HD + h * D + sl * 4);

    float mx = -FLT_MAX, sum = 0.0f;
#pragma unroll 1
    for (int t = 0; t < 23; t++) {
        int s = 2 * t + half;
        bool ok = (s < S);
        int j = sidx[ok ? s : 0];
        float4 kk = *(const float4*)(g_K + ((size_t)b * L + j) * HD + h * D + sl * 4);
        float p = q.x * kk.x + q.y * kk.y + q.z * kk.z + q.w * kk.w;
#pragma unroll
        for (int o = 1; o < 16; o <<= 1) p += __shfl_xor_sync(0xffffffffu, p, o);
        if (ok) { mx = fmaxf(mx, p); sum += p; }
    }
    float mxo  = __shfl_xor_sync(0xffffffffu, mx, 16);
    float sumo = __shfl_xor_sync(0xffffffffu, sum, 16);
    mx = fmaxf(mx, mxo);
    sum += sumo;
    if (lane == 0)
        g_M[((size_t)b * H + h) * L + l] = mx - sum * (1.0f / (float)S);
}

// ---------------- top-45 per (b,h), lowest-index tie-break ----------------
__global__ __launch_bounds__(256) void topk_kernel() {
    int bh = blockIdx.x;
    __shared__ float sv[L];
    __shared__ float rv[256];
    __shared__ int   ri[256];
    int t = threadIdx.x;
    const float* Mrow = g_M + (size_t)bh * L;
    for (int i = t; i < L; i += 256) sv[i] = Mrow[i];
    __syncthreads();
    for (int u = 0; u < U; u++) {
        float best = -FLT_MAX;
        int bi = L;
        for (int i = t; i < L; i += 256) {
            float v = sv[i];
            if (v > best) { best = v; bi = i; }
        }
        rv[t] = best; ri[t] = bi;
        __syncthreads();
        for (int s = 128; s; s >>= 1) {
            if (t < s) {
                if (rv[t + s] > rv[t] || (rv[t + s] == rv[t] && ri[t + s] < ri[t])) {
                    rv[t] = rv[t + s]; ri[t] = ri[t + s];
                }
            }
            __syncthreads();
        }
        if (t == 0) {
            g_topidx[bh * U + u] = ri[0];
            sv[ri[0]] = -FLT_MAX;
        }
        __syncthreads();
    }
}

// ---------------- fused scores+softmax+PV (flash-style, per L-chunk) ----------------
__global__ __launch_bounds__(256) void attn_fused_kernel() {
    extern __shared__ float fs[];
    float* Qs   = fs;                    // 48 x FST
    float* Ks   = Qs + 48 * FST;         // 64 x FST
    float* Vs   = Ks + 64 * FST;         // 64 x FST
    float* Ss   = Vs + 64 * FST;         // 48 x FST
    float* m_sh = Ss + 48 * FST;         // 48
    float* s_sh = m_sh + 48;             // 48
    float* r_sh = s_sh + 48;             // 48

    int chunk = blockIdx.x, bh = blockIdx.y;
    int b = bh >> 3, h = bh & 7;
    int t = threadIdx.x;
    int d = t & 63, ug = t >> 6;
    int l0g = chunk * (L / FCH);

    for (int i = t; i < U * 16; i += 256) {
        int u = i >> 4, c4 = (i & 15) * 4;
        int li = g_topidx[bh * U + u];
        float4 q = *(const float4*)&g_Q[((size_t)b * L + li) * HD + h * D + c4];
        Qs[u * FST + c4 + 0] = q.x;
        Qs[u * FST + c4 + 1] = q.y;
        Qs[u * FST + c4 + 2] = q.z;
        Qs[u * FST + c4 + 3] = q.w;
    }
    if (t < 48) { m_sh[t] = -FLT_MAX; s_sh[t] = 0.0f; }

    float acc[12];
#pragma unroll
    for (int r = 0; r < 12; r++) acc[r] = 0.0f;
    __syncthreads();

    for (int sub = 0; sub < 8; sub++) {
        for (int i = t; i < 64 * 16; i += 256) {
            int r = i >> 4, c4 = (i & 15) * 4;
            size_t base = ((size_t)b * L + l0g + sub * 64 + r) * HD + h * D + c4;
            float4 kk = *(const float4*)&g_K[base];
            Ks[r * FST + c4 + 0] = kk.x; Ks[r * FST + c4 + 1] = kk.y;
            Ks[r * FST + c4 + 2] = kk.z; Ks[r * FST + c4 + 3] = kk.w;
            float4 vv = *(const float4*)&g_V[base];
            Vs[r * FST + c4 + 0] = vv.x; Vs[r * FST + c4 + 1] = vv.y;
            Vs[r * FST + c4 + 2] = vv.z; Vs[r * FST + c4 + 3] = vv.w;
        }
        __syncthreads();

        if (t < 192) {
            int u0 = (t >> 4) * 4, ll0 = (t & 15) * 4;
            float sa[4][4];
#pragma unroll
            for (int j = 0; j < 4; j++)
#pragma unroll
                for (int jj = 0; jj < 4; jj++) sa[j][jj] = 0.0f;
            for (int dd = 0; dd < 64; dd++) {
                float qv[4], kv[4];
#pragma unroll
                for (int j = 0; j < 4; j++) qv[j] = Qs[(u0 + j) * FST + dd];
#pragma unroll
                for (int j = 0; j < 4; j++) kv[j] = Ks[(ll0 + j) * FST + dd];
#pragma unroll
                for (int j = 0; j < 4; j++)
#pragma unroll
                    for (int jj = 0; jj < 4; jj++) sa[j][jj] += qv[j] * kv[jj];
            }
#pragma unroll
            for (int j = 0; j < 4; j++)
#pragma unroll
                for (int jj = 0; jj < 4; jj++)
                    Ss[(u0 + j) * FST + ll0 + jj] = sa[j][jj] * 0.125f;
        }
        __syncthreads();

        if (t < U) {
            float* row = Ss + t * FST;
            float tm = row[0];
            for (int l = 1; l < 64; l++) tm = fmaxf(tm, row[l]);
            float om = m_sh[t];
            float nm = fmaxf(om, tm);
            float rs = __expf(om - nm);
            float se = 0.0f;
            for (int l = 0; l < 64; l++) {
                float e = __expf(row[l] - nm);
                row[l] = e;
                se += e;
            }
            m_sh[t] = nm;
            s_sh[t] = s_sh[t] * rs + se;
            r_sh[t] = rs;
        }
        __syncthreads();

        // PV accumulate: l-outer so Vs[l*FST+d] is loaded once per l (not 12x)
#pragma unroll
        for (int r = 0; r < 12; r++) {
            int u = ug + 4 * r;
            if (u < U) acc[r] *= r_sh[u];
        }
#pragma unroll 4
        for (int l = 0; l < 64; l++) {
            float vv = Vs[l * FST + d];
#pragma unroll
            for (int r = 0; r < 12; r++) {
                int u = ug + 4 * r;
                if (u < U) acc[r] += Ss[u * FST + l] * vv;
            }
        }
        __syncthreads();
    }

#pragma unroll
    for (int r = 0; r < 12; r++) {
        int u = ug + 4 * r;
        if (u < U)
            g_ctxpart[((size_t)bh * FCH + chunk) * (U * D) + u * D + d] = acc[r];
    }
    if (t < U) {
        g_pm[(bh * FCH + chunk) * U + t] = m_sh[t];
        g_ps[(bh * FCH + chunk) * U + t] = s_sh[t];
    }
}

// ---------------- LSE merge across chunks ----------------
__global__ __launch_bounds__(256) void attn_merge_kernel() {
    int i = blockIdx.x * 256 + threadIdx.x;
    if (i >= BH * U * D) return;
    int bh = i / (U * D);
    int rem = i % (U * D);
    int u = rem / D;
    float gm = -FLT_MAX;
#pragma unroll
    for (int c = 0; c < FCH; c++)
        gm = fmaxf(gm, g_pm[(bh * FCH + c) * U + u]);
    float den = 0.0f, num = 0.0f;
#pragma unroll
    for (int c = 0; c < FCH; c++) {
        float w = __expf(g_pm[(bh * FCH + c) * U + u] - gm);
        den += g_ps[(bh * FCH + c) * U + u] * w;
        num += g_ctxpart[((size_t)bh * FCH + c) * (U * D) + rem] * w;
    }
    g_ctxsel[i] = num / den;
}

// ---------------- base_out[b] = concat_h(vmean[b,h]) @ Wo (split-K partials) ----------------
__global__ __launch_bounds__(512) void baseout_part_kernel(const float* __restrict__ Wo) {
    int b = blockIdx.x >> 3, kc = blockIdx.x & 7;
    int n = threadIdx.x;
    float acc = 0.0f;
#pragma unroll 8
    for (int k0 = 0; k0 < 64; k0++) {
        int k = kc * 64 + k0;
        acc += g_vmean[b * 512 + k] * Wo[(size_t)k * 512 + n];
    }
    g_bop[(b * 8 + kc) * 512 + n] = acc;
}

__global__ __launch_bounds__(256) void baseout_reduce_kernel() {
    int i = blockIdx.x * 256 + threadIdx.x;   // < B*512
    int b = i >> 9;
    int n = i & 511;
    float s = 0.0f;
#pragma unroll
    for (int kc = 0; kc < 8; kc++) s += g_bop[(b * 8 + kc) * 512 + n];
    g_baseout[i] = s;
}

// ---------------- slot table: which u selected row l for head h ----------------
__global__ __launch_bounds__(256) void slot_init_kernel() {
    int i = blockIdx.x * 256 + threadIdx.x;
    if (i < BL * H) g_slot[i] = -1;
}

__global__ __launch_bounds__(256) void slot_set_kernel() {
    int i = blockIdx.x * 256 + threadIdx.x;   // < BH*U
    if (i >= BH * U) return;
    int bh = i / U, u = i % U;
    int b = bh >> 3, h = bh & 7;
    int li = g_topidx[bh * U + u];
    g_slot[(b * L + li) * H + h] = u;
}

// ---------------- out[row] = baseout[b] (+ (ctxsel - vmean) @ Wo_block) ----------------
__global__ __launch_bounds__(128) void writeout_kernel(const float* __restrict__ Wo,
                                                       float* __restrict__ out) {
    int row = blockIdx.x;              // 0..BL-1
    int b = row >> 12;
    int t = threadIdx.x;
    __shared__ int sl[8];
    __shared__ float delta[64];
    if (t < 8) sl[t] = g_slot[row * 8 + t];
    __syncthreads();
    int any = 0;
#pragma unroll
    for (int h = 0; h < 8; h++) any |= (sl[h] >= 0);

    int c = t * 4;
    float4 o = *(const float4*)&g_baseout[b * 512 + c];
    if (any) {
        float a0 = 0.0f, a1 = 0.0f, a2 = 0.0f, a3 = 0.0f;
        for (int h = 0; h < 8; h++) {
            int u = sl[h];
            if (u >= 0 && t < 64)
                delta[t] = g_ctxsel[((size_t)(b * 8 + h) * U + u) * 64 + t]
                         - g_vmean[(b * 8 + h) * 64 + t];
            __syncthreads();
            if (u >= 0) {
#pragma unroll 8
                for (int d = 0; d < 64; d++) {
                    float dv = delta[d];
                    float4 w = *(const float4*)&Wo[(size_t)(h * 64 + d) * 512 + c];
                    a0 += dv * w.x; a1 += dv * w.y; a2 += dv * w.z; a3 += dv * w.w;
                }
            }
            __syncthreads();
        }
        o.x += a0; o.y += a1; o.z += a2; o.w += a3;
    }
    *(float4*)&out[(size_t)row * 512 + c] = o;
}

// ---------------- launch ----------------
extern "C" void kernel_launch(void* const* d_in, const int* in_sizes, int n_in,
                              void* d_out, int out_size) {
    const float* x  = (const float*)d_in[0];
    const float* Wq = (const float*)d_in[1];
    const float* Wk = (const float*)d_in[2];
    const float* Wv = (const float*)d_in[3];
    const float* Wo = (const float*)d_in[4];
    const int*   idx = (const int*)d_in[5];
    float* out = (float*)d_out;

    __half *x0, *x1, *W2qk, *W2v;
    float *Q, *K, *V;
    cudaGetSymbolAddress((void**)&x0, g_x0);
    cudaGetSymbolAddress((void**)&x1, g_x1);
    cudaGetSymbolAddress((void**)&W2qk, g_W2qk);
    cudaGetSymbolAddress((void**)&W2v,  g_W2v);
    cudaGetSymbolAddress((void**)&Q, g_Q);
    cudaGetSymbolAddress((void**)&K, g_K);
    cudaGetSymbolAddress((void**)&V, g_V);

    const int FSMEM = (48 * FST + 64 * FST + 64 * FST + 48 * FST + 144) * 4;
    cudaFuncSetAttribute(attn_fused_kernel, cudaFuncAttributeMaxDynamicSharedMemorySize, FSMEM);

    split_x_kernel<<<(BL * HD) / 1024, 256>>>(x);
    build_w2_kernel<<<1024, 256>>>(Wq, W2qk, 1024, 0);
    build_w2_kernel<<<1024, 256>>>(Wk, W2qk, 1024, 512);
    build_w2_kernel<<<1024, 256>>>(Wv, W2v, 512, 0);

    // Q,K projection (N=1024 -> Q cols then K cols), Ktot=1536
    gemm_f16<<<dim3(8, 128), 256>>>(x0, x1, W2qk, 1024, Q, K);
    // V projection
    gemm_f16<<<dim3(4, 128), 256>>>(x0, x1, W2v, 512, V, V);

    vmean_part_kernel<<<256, 256>>>();
    vmean_reduce_kernel<<<8, 256>>>();
    compute_M_kernel<<<BL, 256>>>(idx);
    topk_kernel<<<BH, 256>>>();

    attn_fused_kernel<<<dim3(FCH, BH), 256, FSMEM>>>();
    attn_merge_kernel<<<(BH * U * D + 255) / 256, 256>>>();

    // O projection replacement: base GEMV + slot table + direct write with corrections
    baseout_part_kernel<<<B * 8, 512>>>(Wo);
    baseout_reduce_kernel<<<(B * HD) / 256, 256>>>();
    slot_init_kernel<<<(BL * H) / 256, 256>>>();
    slot_set_kernel<<<(BH * U + 255) / 256, 256>>>();
    writeout_kernel<<<BL, 128>>>(Wo, out);
}

// round 15
// speedup vs baseline: 1.7586x; 1.0182x over previous
#include <cuda_runtime.h>
#include <cuda_fp16.h>
#include <float.h>
#include <stdint.h>

// Problem constants
#define B   4
#define L   4096
#define HD  512
#define H   8
#define D   64
#define S   45
#define U   45
#define BL  (B * L)            // 16384
#define BH  (B * H)            // 32
#define FCH 16                 // L-chunks for fused attention
#define NSUB ((L / FCH) / 64)  // 4 subtiles per chunk
#define FST 65                 // smem row stride (floats)

// ---------------- device scratch (static; no runtime allocation) ----------------
__device__ __half g_x0[BL * HD];
__device__ __half g_x1[BL * HD];
__device__ __half g_W2qk[1536 * 1024];   // [Ktot=1536][N=1024] stacked [Wq|Wk]
__device__ __half g_W2v[1536 * 512];     // [Ktot=1536][N=512]
__device__ float g_Q[BL * HD];
__device__ float g_K[BL * HD];
__device__ float g_V[BL * HD];
__device__ float g_M[BH * L];
__device__ int   g_topidx[BH * U];
__device__ float g_vmeanpart[BH * 8 * D];
__device__ float g_vmean[BH * D];
__device__ float g_ctxpart[BH * FCH * U * D];
__device__ float g_pm[BH * FCH * U];
__device__ float g_ps[BH * FCH * U];
__device__ float g_ctxsel[BH * U * D];
__device__ float g_bop[B * 8 * HD];      // base_out split-K partials
__device__ float g_baseout[B * HD];      // vmean-concat @ Wo per batch
__device__ int   g_slot[BL * H];         // selecting u per (row,h), -1 = none

static __device__ __forceinline__ unsigned short h16u(__half v) {
    return *(unsigned short*)&v;
}

// ---------------- split x into 2 fp16 residual levels ----------------
__global__ __launch_bounds__(256) void split_x_kernel(const float* __restrict__ x) {
    size_t i = ((size_t)blockIdx.x * 256 + threadIdx.x) * 4;
    float4 v = *(const float4*)(x + i);
    float vv[4] = {v.x, v.y, v.z, v.w};
    unsigned short h0[4], h1[4];
#pragma unroll
    for (int j = 0; j < 4; j++) {
        __half a0 = __float2half_rn(vv[j]);
        __half a1 = __float2half_rn(vv[j] - __half2float(a0));
        h0[j] = h16u(a0); h1[j] = h16u(a1);
    }
    uint2 p;
    p.x = h0[0] | ((uint32_t)h0[1] << 16); p.y = h0[2] | ((uint32_t)h0[3] << 16);
    *(uint2*)&g_x0[i] = p;
    p.x = h1[0] | ((uint32_t)h1[1] << 16); p.y = h1[2] | ((uint32_t)h1[3] << 16);
    *(uint2*)&g_x1[i] = p;
}

// ---------------- build stacked split-W [Ktot=1536][N]; sections {w0,w1,w0} ----------------
__global__ __launch_bounds__(256) void build_w2_kernel(const float* __restrict__ W,
                                                       __half* __restrict__ out,
                                                       int outW, int colOff) {
    int id = blockIdx.x * 256 + threadIdx.x;   // < 512*512
    int r = id >> 9, c = id & 511;
    float v = W[id];
    __half b0 = __float2half_rn(v);
    __half b1 = __float2half_rn(v - __half2float(b0));
    out[(size_t)r * outW + colOff + c] = b0;
    out[(size_t)(512 + r) * outW + colOff + c] = b1;
    out[(size_t)(1024 + r) * outW + colOff + c] = b0;
}

// ---------------- fp16 split GEMM via mma.sync (register-staged, proven) ----------------
__global__ __launch_bounds__(256) void gemm_f16(
    const __half* __restrict__ A0, const __half* __restrict__ A1,
    const __half* __restrict__ W2, int Nw,
    float* __restrict__ o0, float* __restrict__ o1)
{
    __shared__ __half As[2][128][40];
    __shared__ __half Bs[2][32][136];

    int tid = threadIdx.x;
    int warp = tid >> 5, lane = tid & 31;
    int bm = blockIdx.y * 128;
    int bn = blockIdx.x * 128;
    int wm = (warp >> 2) * 64;
    int wn = (warp & 3) * 32;

    float acc[4][4][4];
#pragma unroll
    for (int mi = 0; mi < 4; mi++)
#pragma unroll
        for (int ni = 0; ni < 4; ni++)
#pragma unroll
            for (int r = 0; r < 4; r++) acc[mi][ni][r] = 0.0f;

    int arow0 = tid >> 2;
    int acol0 = (tid & 3) * 8;
    int brow0 = tid >> 4;
    int bcol0 = (tid & 15) * 8;

    const int kiter = 1536 / 32;
    uint4 ra0, ra1, rb0, rb1;

    {
        ra0 = *(const uint4*)&A0[(size_t)(bm + arow0) * HD + acol0];
        ra1 = *(const uint4*)&A0[(size_t)(bm + 64 + arow0) * HD + acol0];
        rb0 = *(const uint4*)&W2[(size_t)brow0 * Nw + bn + bcol0];
        rb1 = *(const uint4*)&W2[(size_t)(16 + brow0) * Nw + bn + bcol0];
        *(uint4*)&As[0][arow0][acol0]      = ra0;
        *(uint4*)&As[0][64 + arow0][acol0] = ra1;
        *(uint4*)&Bs[0][brow0][bcol0]      = rb0;
        *(uint4*)&Bs[0][16 + brow0][bcol0] = rb1;
    }
    __syncthreads();

    int cur = 0;
    for (int it = 0; it < kiter; it++) {
        if (it + 1 < kiter) {
            int kk0 = (it + 1) * 32;
            const __half* Asrc = (kk0 >= 1024) ? A1 : A0;
            int scol = kk0 & 511;
            ra0 = *(const uint4*)&Asrc[(size_t)(bm + arow0) * HD + scol + acol0];
            ra1 = *(const uint4*)&Asrc[(size_t)(bm + 64 + arow0) * HD + scol + acol0];
            rb0 = *(const uint4*)&W2[(size_t)(kk0 + brow0) * Nw + bn + bcol0];
            rb1 = *(const uint4*)&W2[(size_t)(kk0 + 16 + brow0) * Nw + bn + bcol0];
        }
#pragma unroll
        for (int ks = 0; ks < 32; ks += 16) {
            uint32_t af[4][4], bfr[4][2];
#pragma unroll
            for (int mi = 0; mi < 4; mi++) {
                uint32_t addr = (uint32_t)__cvta_generic_to_shared(
                    &As[cur][wm + mi * 16 + (lane & 15)][ks + ((lane >> 4) << 3)]);
                asm volatile("ldmatrix.sync.aligned.m8n8.x4.shared.b16 {%0,%1,%2,%3}, [%4];\n"
                             : "=r"(af[mi][0]), "=r"(af[mi][1]), "=r"(af[mi][2]), "=r"(af[mi][3])
                             : "r"(addr));
            }
#pragma unroll
            for (int ni = 0; ni < 4; ni++) {
                uint32_t addr = (uint32_t)__cvta_generic_to_shared(
                    &Bs[cur][ks + (lane & 15)][wn + ni * 8]);
                asm volatile("ldmatrix.sync.aligned.m8n8.x2.trans.shared.b16 {%0,%1}, [%2];\n"
                             : "=r"(bfr[ni][0]), "=r"(bfr[ni][1]) : "r"(addr));
            }
#pragma unroll
            for (int mi = 0; mi < 4; mi++)
#pragma unroll
                for (int ni = 0; ni < 4; ni++) {
                    asm volatile(
                        "mma.sync.aligned.m16n8k16.row.col.f32.f16.f16.f32 "
                        "{%0,%1,%2,%3}, {%4,%5,%6,%7}, {%8,%9}, {%0,%1,%2,%3};\n"
                        : "+f"(acc[mi][ni][0]), "+f"(acc[mi][ni][1]),
                          "+f"(acc[mi][ni][2]), "+f"(acc[mi][ni][3])
                        : "r"(af[mi][0]), "r"(af[mi][1]), "r"(af[mi][2]), "r"(af[mi][3]),
                          "r"(bfr[ni][0]), "r"(bfr[ni][1]));
                }
        }
        if (it + 1 < kiter) {
            int nb = cur ^ 1;
            *(uint4*)&As[nb][arow0][acol0]      = ra0;
            *(uint4*)&As[nb][64 + arow0][acol0] = ra1;
            *(uint4*)&Bs[nb][brow0][bcol0]      = rb0;
            *(uint4*)&Bs[nb][16 + brow0][bcol0] = rb1;
            __syncthreads();
            cur ^= 1;
        }
    }

    float* O = (bn >= 512) ? o1 : o0;
    int nb0 = bn & 511;
#pragma unroll
    for (int mi = 0; mi < 4; mi++) {
        int r = bm + wm + mi * 16 + (lane >> 2);
#pragma unroll
        for (int ni = 0; ni < 4; ni++) {
            int c = nb0 + wn + ni * 8 + ((lane & 3) << 1);
            float2 v0 = make_float2(acc[mi][ni][0], acc[mi][ni][1]);
            float2 v1 = make_float2(acc[mi][ni][2], acc[mi][ni][3]);
            *(float2*)&O[(size_t)r * HD + c] = v0;
            *(float2*)&O[(size_t)(r + 8) * HD + c] = v1;
        }
    }
}

// ---------------- v mean over L per (b,h,d) ----------------
__global__ __launch_bounds__(256) void vmean_part_kernel() {
    int bh = blockIdx.x & 31, part = blockIdx.x >> 5;
    int b = bh >> 3, h = bh & 7;
    int t = threadIdx.x;
    int d = t & 63, sub = t >> 6;
    const float* base = g_V + (size_t)b * L * HD + h * D + d;
    float s = 0.0f;
    int lend = (part + 1) * 512;
    for (int l = part * 512 + sub; l < lend; l += 4) s += base[(size_t)l * HD];
    __shared__ float sm[256];
    sm[t] = s;
    __syncthreads();
    if (t < 64)
        g_vmeanpart[(bh * 8 + part) * D + t] = sm[t] + sm[t + 64] + sm[t + 128] + sm[t + 192];
}

__global__ __launch_bounds__(256) void vmean_reduce_kernel() {
    int i = blockIdx.x * 256 + threadIdx.x;
    if (i >= BH * D) return;
    int bh = i >> 6, d = i & 63;
    float s = 0.0f;
#pragma unroll
    for (int p = 0; p < 8; p++) s += g_vmeanpart[(bh * 8 + p) * D + d];
    g_vmean[i] = s * (1.0f / (float)L);
}

// ---------------- M[b,h,l] = max_s(qk) - mean_s(qk) ----------------
__global__ __launch_bounds__(256) void compute_M_kernel(const int* __restrict__ idx) {
    int bl = blockIdx.x;
    int b = bl >> 12;
    int l = bl & (L - 1);
    int h = threadIdx.x >> 5;
    int lane = threadIdx.x & 31;
    int half = lane >> 4, sl = lane & 15;

    __shared__ int sidx[S];
    if (threadIdx.x < S) sidx[threadIdx.x] = idx[l * S + threadIdx.x];
    __syncthreads();

    float4 q = *(const float4*)(g_Q + (size_t)bl * HD + h * D + sl * 4);

    float mx = -FLT_MAX, sum = 0.0f;
#pragma unroll 1
    for (int t = 0; t < 23; t++) {
        int s = 2 * t + half;
        bool ok = (s < S);
        int j = sidx[ok ? s : 0];
        float4 kk = *(const float4*)(g_K + ((size_t)b * L + j) * HD + h * D + sl * 4);
        float p = q.x * kk.x + q.y * kk.y + q.z * kk.z + q.w * kk.w;
#pragma unroll
        for (int o = 1; o < 16; o <<= 1) p += __shfl_xor_sync(0xffffffffu, p, o);
        if (ok) { mx = fmaxf(mx, p); sum += p; }
    }
    float mxo  = __shfl_xor_sync(0xffffffffu, mx, 16);
    float sumo = __shfl_xor_sync(0xffffffffu, sum, 16);
    mx = fmaxf(mx, mxo);
    sum += sumo;
    if (lane == 0)
        g_M[((size_t)b * H + h) * L + l] = mx - sum * (1.0f / (float)S);
}

// ---------------- top-45 per (b,h), lowest-index tie-break ----------------
__global__ __launch_bounds__(256) void topk_kernel() {
    int bh = blockIdx.x;
    __shared__ float sv[L];
    __shared__ float rv[256];
    __shared__ int   ri[256];
    int t = threadIdx.x;
    const float* Mrow = g_M + (size_t)bh * L;
    for (int i = t; i < L; i += 256) sv[i] = Mrow[i];
    __syncthreads();
    for (int u = 0; u < U; u++) {
        float best = -FLT_MAX;
        int bi = L;
        for (int i = t; i < L; i += 256) {
            float v = sv[i];
            if (v > best) { best = v; bi = i; }
        }
        rv[t] = best; ri[t] = bi;
        __syncthreads();
        for (int s = 128; s; s >>= 1) {
            if (t < s) {
                if (rv[t + s] > rv[t] || (rv[t + s] == rv[t] && ri[t + s] < ri[t])) {
                    rv[t] = rv[t + s]; ri[t] = ri[t + s];
                }
            }
            __syncthreads();
        }
        if (t == 0) {
            g_topidx[bh * U + u] = ri[0];
            sv[ri[0]] = -FLT_MAX;
        }
        __syncthreads();
    }
}

// ---------------- fused scores+softmax+PV (flash-style, per L-chunk) ----------------
__global__ __launch_bounds__(256) void attn_fused_kernel() {
    extern __shared__ float fs[];
    float* Qs   = fs;                    // 48 x FST
    float* Ks   = Qs + 48 * FST;         // 64 x FST
    float* Vs   = Ks + 64 * FST;         // 64 x FST
    float* Ss   = Vs + 64 * FST;         // 48 x FST
    float* m_sh = Ss + 48 * FST;         // 48
    float* s_sh = m_sh + 48;             // 48
    float* r_sh = s_sh + 48;             // 48

    int chunk = blockIdx.x, bh = blockIdx.y;
    int b = bh >> 3, h = bh & 7;
    int t = threadIdx.x;
    int d = t & 63, ug = t >> 6;
    int l0g = chunk * (L / FCH);

    for (int i = t; i < U * 16; i += 256) {
        int u = i >> 4, c4 = (i & 15) * 4;
        int li = g_topidx[bh * U + u];
        float4 q = *(const float4*)&g_Q[((size_t)b * L + li) * HD + h * D + c4];
        Qs[u * FST + c4 + 0] = q.x;
        Qs[u * FST + c4 + 1] = q.y;
        Qs[u * FST + c4 + 2] = q.z;
        Qs[u * FST + c4 + 3] = q.w;
    }
    if (t < 48) { m_sh[t] = -FLT_MAX; s_sh[t] = 0.0f; }

    float acc[12];
#pragma unroll
    for (int r = 0; r < 12; r++) acc[r] = 0.0f;
    __syncthreads();

    for (int sub = 0; sub < NSUB; sub++) {
        for (int i = t; i < 64 * 16; i += 256) {
            int r = i >> 4, c4 = (i & 15) * 4;
            size_t base = ((size_t)b * L + l0g + sub * 64 + r) * HD + h * D + c4;
            float4 kk = *(const float4*)&g_K[base];
            Ks[r * FST + c4 + 0] = kk.x; Ks[r * FST + c4 + 1] = kk.y;
            Ks[r * FST + c4 + 2] = kk.z; Ks[r * FST + c4 + 3] = kk.w;
            float4 vv = *(const float4*)&g_V[base];
            Vs[r * FST + c4 + 0] = vv.x; Vs[r * FST + c4 + 1] = vv.y;
            Vs[r * FST + c4 + 2] = vv.z; Vs[r * FST + c4 + 3] = vv.w;
        }
        __syncthreads();

        if (t < 192) {
            int u0 = (t >> 4) * 4, ll0 = (t & 15) * 4;
            float sa[4][4];
#pragma unroll
            for (int j = 0; j < 4; j++)
#pragma unroll
                for (int jj = 0; jj < 4; jj++) sa[j][jj] = 0.0f;
            for (int dd = 0; dd < 64; dd++) {
                float qv[4], kv[4];
#pragma unroll
                for (int j = 0; j < 4; j++) qv[j] = Qs[(u0 + j) * FST + dd];
#pragma unroll
                for (int j = 0; j < 4; j++) kv[j] = Ks[(ll0 + j) * FST + dd];
#pragma unroll
                for (int j = 0; j < 4; j++)
#pragma unroll
                    for (int jj = 0; jj < 4; jj++) sa[j][jj] += qv[j] * kv[jj];
            }
#pragma unroll
            for (int j = 0; j < 4; j++)
#pragma unroll
                for (int jj = 0; jj < 4; jj++)
                    Ss[(u0 + j) * FST + ll0 + jj] = sa[j][jj] * 0.125f;
        }
        __syncthreads();

        if (t < U) {
            float* row = Ss + t * FST;
            float tm = row[0];
            for (int l = 1; l < 64; l++) tm = fmaxf(tm, row[l]);
            float om = m_sh[t];
            float nm = fmaxf(om, tm);
            float rs = __expf(om - nm);
            float se = 0.0f;
            for (int l = 0; l < 64; l++) {
                float e = __expf(row[l] - nm);
                row[l] = e;
                se += e;
            }
            m_sh[t] = nm;
            s_sh[t] = s_sh[t] * rs + se;
            r_sh[t] = rs;
        }
        __syncthreads();

        // PV accumulate: l-outer so Vs[l*FST+d] loaded once per l
#pragma unroll
        for (int r = 0; r < 12; r++) {
            int u = ug + 4 * r;
            if (u < U) acc[r] *= r_sh[u];
        }
#pragma unroll 4
        for (int l = 0; l < 64; l++) {
            float vv = Vs[l * FST + d];
#pragma unroll
            for (int r = 0; r < 12; r++) {
                int u = ug + 4 * r;
                if (u < U) acc[r] += Ss[u * FST + l] * vv;
            }
        }
        __syncthreads();
    }

#pragma unroll
    for (int r = 0; r < 12; r++) {
        int u = ug + 4 * r;
        if (u < U)
            g_ctxpart[((size_t)bh * FCH + chunk) * (U * D) + u * D + d] = acc[r];
    }
    if (t < U) {
        g_pm[(bh * FCH + chunk) * U + t] = m_sh[t];
        g_ps[(bh * FCH + chunk) * U + t] = s_sh[t];
    }
}

// ---------------- LSE merge across chunks ----------------
__global__ __launch_bounds__(256) void attn_merge_kernel() {
    int i = blockIdx.x * 256 + threadIdx.x;
    if (i >= BH * U * D) return;
    int bh = i / (U * D);
    int rem = i % (U * D);
    int u = rem / D;
    float gm = -FLT_MAX;
#pragma unroll
    for (int c = 0; c < FCH; c++)
        gm = fmaxf(gm, g_pm[(bh * FCH + c) * U + u]);
    float den = 0.0f, num = 0.0f;
#pragma unroll
    for (int c = 0; c < FCH; c++) {
        float w = __expf(g_pm[(bh * FCH + c) * U + u] - gm);
        den += g_ps[(bh * FCH + c) * U + u] * w;
        num += g_ctxpart[((size_t)bh * FCH + c) * (U * D) + rem] * w;
    }
    g_ctxsel[i] = num / den;
}

// ---------------- base_out[b] = concat_h(vmean[b,h]) @ Wo (split-K partials) ----------------
__global__ __launch_bounds__(512) void baseout_part_kernel(const float* __restrict__ Wo) {
    int b = blockIdx.x >> 3, kc = blockIdx.x & 7;
    int n = threadIdx.x;
    float acc = 0.0f;
#pragma unroll 8
    for (int k0 = 0; k0 < 64; k0++) {
        int k = kc * 64 + k0;
        acc += g_vmean[b * 512 + k] * Wo[(size_t)k * 512 + n];
    }
    g_bop[(b * 8 + kc) * 512 + n] = acc;
}

__global__ __launch_bounds__(256) void baseout_reduce_kernel() {
    int i = blockIdx.x * 256 + threadIdx.x;   // < B*512
    int b = i >> 9;
    int n = i & 511;
    float s = 0.0f;
#pragma unroll
    for (int kc = 0; kc < 8; kc++) s += g_bop[(b * 8 + kc) * 512 + n];
    g_baseout[i] = s;
}

// ---------------- slot table ----------------
__global__ __launch_bounds__(256) void slot_init_kernel() {
    int i = blockIdx.x * 256 + threadIdx.x;
    if (i < BL * H) g_slot[i] = -1;
}

__global__ __launch_bounds__(256) void slot_set_kernel() {
    int i = blockIdx.x * 256 + threadIdx.x;   // < BH*U
    if (i >= BH * U) return;
    int bh = i / U, u = i % U;
    int b = bh >> 3, h = bh & 7;
    int li = g_topidx[bh * U + u];
    g_slot[(b * L + li) * H + h] = u;
}

// ---------------- out[row] = baseout[b] (+ (ctxsel - vmean) @ Wo_block) ----------------
__global__ __launch_bounds__(128) void writeout_kernel(const float* __restrict__ Wo,
                                                       float* __restrict__ out) {
    int row = blockIdx.x;              // 0..BL-1
    int b = row >> 12;
    int t = threadIdx.x;
    __shared__ int sl[8];
    __shared__ float delta[64];
    if (t < 8) sl[t] = g_slot[row * 8 + t];
    __syncthreads();
    int any = 0;
#pragma unroll
    for (int h = 0; h < 8; h++) any |= (sl[h] >= 0);

    int c = t * 4;
    float4 o = *(const float4*)&g_baseout[b * 512 + c];
    if (any) {
        float a0 = 0.0f, a1 = 0.0f, a2 = 0.0f, a3 = 0.0f;
        for (int h = 0; h < 8; h++) {
            int u = sl[h];
            if (u >= 0 && t < 64)
                delta[t] = g_ctxsel[((size_t)(b * 8 + h) * U + u) * 64 + t]
                         - g_vmean[(b * 8 + h) * 64 + t];
            __syncthreads();
            if (u >= 0) {
#pragma unroll 8
                for (int d = 0; d < 64; d++) {
                    float dv = delta[d];
                    float4 w = *(const float4*)&Wo[(size_t)(h * 64 + d) * 512 + c];
                    a0 += dv * w.x; a1 += dv * w.y; a2 += dv * w.z; a3 += dv * w.w;
                }
            }
            __syncthreads();
        }
        o.x += a0; o.y += a1; o.z += a2; o.w += a3;
    }
    *(float4*)&out[(size_t)row * 512 + c] = o;
}

// ---------------- launch (fork-join: V-chain overlaps M-chain) ----------------
extern "C" void kernel_launch(void* const* d_in, const int* in_sizes, int n_in,
                              void* d_out, int out_size) {
    const float* x  = (const float*)d_in[0];
    const float* Wq = (const float*)d_in[1];
    const float* Wk = (const float*)d_in[2];
    const float* Wv = (const float*)d_in[3];
    const float* Wo = (const float*)d_in[4];
    const int*   idx = (const int*)d_in[5];
    float* out = (float*)d_out;

    __half *x0, *x1, *W2qk, *W2v;
    float *Q, *K, *V;
    cudaGetSymbolAddress((void**)&x0, g_x0);
    cudaGetSymbolAddress((void**)&x1, g_x1);
    cudaGetSymbolAddress((void**)&W2qk, g_W2qk);
    cudaGetSymbolAddress((void**)&W2v,  g_W2v);
    cudaGetSymbolAddress((void**)&Q, g_Q);
    cudaGetSymbolAddress((void**)&K, g_K);
    cudaGetSymbolAddress((void**)&V, g_V);

    const int FSMEM = (48 * FST + 64 * FST + 64 * FST + 48 * FST + 144) * 4;
    cudaFuncSetAttribute(attn_fused_kernel, cudaFuncAttributeMaxDynamicSharedMemorySize, FSMEM);

    cudaStream_t s0 = 0;
    cudaStream_t s2 = 0;
    cudaEvent_t e0 = 0, e1 = 0, e2 = 0;
    bool forked = (cudaStreamCreateWithFlags(&s2, cudaStreamNonBlocking) == cudaSuccess);
    if (forked) {
        forked = (cudaEventCreateWithFlags(&e0, cudaEventDisableTiming) == cudaSuccess) &&
                 (cudaEventCreateWithFlags(&e1, cudaEventDisableTiming) == cudaSuccess) &&
                 (cudaEventCreateWithFlags(&e2, cudaEventDisableTiming) == cudaSuccess);
        if (!forked) s2 = 0;   // fall back to fully serial on stream 0
    }
    // NOTE: streams/events are intentionally leaked (created ~2x per process;
    // destroying mid-capture is illegal). No device memory is allocated.

    if (forked) { cudaEventRecord(e0, s0); cudaStreamWaitEvent(s2, e0, 0); }

    // s2 early: no data deps
    slot_init_kernel<<<(BL * H) / 256, 256, 0, s2>>>();
    build_w2_kernel<<<1024, 256, 0, s2>>>(Wv, W2v, 512, 0);

    // s0: input split
    split_x_kernel<<<(BL * HD) / 1024, 256, 0, s0>>>(x);
    if (forked) { cudaEventRecord(e1, s0); cudaStreamWaitEvent(s2, e1, 0); }

    // s0: QK chain
    build_w2_kernel<<<1024, 256, 0, s0>>>(Wq, W2qk, 1024, 0);
    build_w2_kernel<<<1024, 256, 0, s0>>>(Wk, W2qk, 1024, 512);
    gemm_f16<<<dim3(8, 128), 256, 0, s0>>>(x0, x1, W2qk, 1024, Q, K);

    // s2: V chain (after split_x)
    gemm_f16<<<dim3(4, 128), 256, 0, s2>>>(x0, x1, W2v, 512, V, V);
    vmean_part_kernel<<<256, 256, 0, s2>>>();
    vmean_reduce_kernel<<<8, 256, 0, s2>>>();
    baseout_part_kernel<<<B * 8, 512, 0, s2>>>(Wo);
    baseout_reduce_kernel<<<(B * HD) / 256, 256, 0, s2>>>();
    if (forked) cudaEventRecord(e2, s2);

    // s0: M chain (overlaps s2)
    compute_M_kernel<<<BL, 256, 0, s0>>>(idx);
    topk_kernel<<<BH, 256, 0, s0>>>();

    // join
    if (forked) cudaStreamWaitEvent(s0, e2, 0);

    slot_set_kernel<<<(BH * U + 255) / 256, 256, 0, s0>>>();
    attn_fused_kernel<<<dim3(FCH, BH), 256, FSMEM, s0>>>();
    attn_merge_kernel<<<(BH * U * D + 255) / 256, 256, 0, s0>>>();
    writeout_kernel<<<BL, 128, 0, s0>>>(Wo, out);
}